// round 11
// baseline (speedup 1.0000x reference)
#include <cuda_runtime.h>
#include <cuda_bf16.h>
#include <math.h>
#include <string.h>

#define BATCH 8
#define C 256
#define NPIX 4096
#define HIMG 64
#define WIMG 64
#define MRED 256
#define HEADS 8
#define HD 32
#define ATTN_SCALE 0.17677669529663687f
#define EPS 1e-5f

// ---------------- scratch ----------------------------------------------------
__device__ float g_kvred[BATCH * MRED * C];   // (b, m, c)
// pre-split bf16 operands
__device__ __nv_bfloat16 g_xh[BATCH * NPIX * C], g_xl[BATCH * NPIX * C];
__device__ __nv_bfloat16 g_wqh[C * C], g_wql[C * C];
__device__ __nv_bfloat16 g_wkvh[2 * C * C], g_wkvl[2 * C * C];
__device__ __nv_bfloat16 g_kv2h[BATCH * MRED * C], g_kv2l[BATCH * MRED * C];
// q projection, pre-scaled hi/lo bf16 (b*n, c)
__device__ __nv_bfloat16 g_qh[BATCH * NPIX * C], g_ql[BATCH * NPIX * C];
// kv projection: K hi/lo split + V bf16, all (b, m, c)
__device__ __nv_bfloat16 g_kh[BATCH * MRED * C], g_kl[BATCH * MRED * C];
__device__ __nv_bfloat16 g_v[BATCH * MRED * C];
// transposed conv weights [k][c]
__device__ float g_w7t[49 * C];
__device__ float g_lwt[9 * C];

// ---------------- helpers ------------------------------------------------------
__device__ __forceinline__ unsigned smem_u32(const void* p) {
    unsigned a;
    asm("{ .reg .u64 t; cvta.to.shared.u64 t, %1; cvt.u32.u64 %0, t; }"
        : "=r"(a) : "l"(p));
    return a;
}
__device__ __forceinline__ void cp16(unsigned dst, const void* src) {
    asm volatile("cp.async.ca.shared.global [%0], [%1], 16;"
                 :: "r"(dst), "l"(src));
}
#define CP_COMMIT() asm volatile("cp.async.commit_group;" ::: "memory")
#define CP_WAIT(n)  asm volatile("cp.async.wait_group %0;" :: "n"(n) : "memory")

__device__ __forceinline__ void ldmx4(unsigned* r, unsigned addr) {
    asm volatile("ldmatrix.sync.aligned.m8n8.x4.shared.b16 {%0,%1,%2,%3}, [%4];"
                 : "=r"(r[0]), "=r"(r[1]), "=r"(r[2]), "=r"(r[3]) : "r"(addr));
}
__device__ __forceinline__ void mma_bf16(float* c, const unsigned* a,
                                         unsigned b0, unsigned b1) {
    asm volatile(
        "mma.sync.aligned.m16n8k16.row.col.f32.bf16.bf16.f32 "
        "{%0,%1,%2,%3}, {%4,%5,%6,%7}, {%8,%9}, {%0,%1,%2,%3};"
        : "+f"(c[0]), "+f"(c[1]), "+f"(c[2]), "+f"(c[3])
        : "r"(a[0]), "r"(a[1]), "r"(a[2]), "r"(a[3]), "r"(b0), "r"(b1));
}
__device__ __forceinline__ unsigned pack_bf16x2(float lo, float hi) {
    unsigned d;
    asm("cvt.rn.bf16x2.f32 %0, %1, %2;" : "=r"(d) : "f"(hi), "f"(lo));
    return d;
}
__device__ __forceinline__ void split_store(__nv_bfloat16* hi, __nv_bfloat16* lo,
                                            size_t idx, float a0, float a1) {
    __nv_bfloat16 h0 = __float2bfloat16(a0);
    __nv_bfloat16 h1 = __float2bfloat16(a1);
    *(__nv_bfloat162*)(hi + idx) = __nv_bfloat162(h0, h1);
    *(__nv_bfloat162*)(lo + idx) = __nv_bfloat162(
        __float2bfloat16(a0 - __bfloat162float(h0)),
        __float2bfloat16(a1 - __bfloat162float(h1)));
}

// ---------------- weights prep: Wq/Wkv split + conv-weight transpose ----------
__global__ __launch_bounds__(256) void prep_weights_kernel(
    const float* __restrict__ Wq, const float* __restrict__ Wkv,
    const float* __restrict__ w7, const float* __restrict__ lw) {
    int bx = blockIdx.x, tid = threadIdx.x;
    if (bx < 64) {                       // Wq: 16384 float4
        int i = bx * 256 + tid;
        float4 v = ((const float4*)Wq)[i];
        split_store(g_wqh, g_wql, 4 * (size_t)i, v.x, v.y);
        split_store(g_wqh, g_wql, 4 * (size_t)i + 2, v.z, v.w);
    } else if (bx < 192) {               // Wkv: 32768 float4
        int i = (bx - 64) * 256 + tid;
        float4 v = ((const float4*)Wkv)[i];
        split_store(g_wkvh, g_wkvl, 4 * (size_t)i, v.x, v.y);
        split_store(g_wkvh, g_wkvl, 4 * (size_t)i + 2, v.z, v.w);
    } else {                             // conv weight transpose, k = bx-192
        int k = bx - 192;
        g_w7t[k * C + tid] = w7[tid * 49 + k];
        if (k < 9) g_lwt[k * C + tid] = lw[tid * 9 + k];
    }
}

// ---------------- HMMA GEMM, bf16-split inputs + cp.async double buffer -------
// EPI 0: q-style (scale then hi/lo split out). EPI 1: kv-style (K split, V bf16).
#define GSTR 40
template <int BM, int EPI>
__global__ __launch_bounds__(256, 2) void gemm_mma_kernel(
    const __nv_bfloat16* __restrict__ Xh, const __nv_bfloat16* __restrict__ Xl,
    const __nv_bfloat16* __restrict__ Wh, const __nv_bfloat16* __restrict__ Wl,
    const float* __restrict__ bias,
    __nv_bfloat16* __restrict__ Oh, __nv_bfloat16* __restrict__ Ol,
    __nv_bfloat16* __restrict__ Ov, float scale) {
    constexpr int MT = BM / 64;
    constexpr int SX = BM * GSTR;
    constexpr int SW = 128 * GSTR;
    constexpr int STG = 2 * SX + 2 * SW;
    extern __shared__ __nv_bfloat16 gsm[];

    int tid = threadIdx.x, lane = tid & 31, w = tid >> 5;
    int bm = blockIdx.x * BM, bn = blockIdx.y * 128;
    int wm = (w & 3) * (16 * MT), wn = (w >> 2) * 64;
    int lr = tid >> 2, lch = (tid & 3) * 8;

    float acc[MT][8][4];
    #pragma unroll
    for (int mt = 0; mt < MT; mt++)
        #pragma unroll
        for (int nt = 0; nt < 8; nt++)
            #pragma unroll
            for (int q = 0; q < 4; q++) acc[mt][nt][q] = 0.f;

    #define XH(s) (gsm + (s) * STG)
    #define XL(s) (gsm + (s) * STG + SX)
    #define WH(s) (gsm + (s) * STG + 2 * SX)
    #define WL(s) (gsm + (s) * STG + 2 * SX + SW)

    #define LOAD_STAGE(s, kc) do {                                            \
        _Pragma("unroll")                                                      \
        for (int rr = 0; rr < MT; rr++) {                                      \
            cp16(smem_u32(XH(s) + (lr + 64 * rr) * GSTR + lch),                \
                 Xh + (size_t)(bm + lr + 64 * rr) * C + (kc) + lch);           \
            cp16(smem_u32(XL(s) + (lr + 64 * rr) * GSTR + lch),                \
                 Xl + (size_t)(bm + lr + 64 * rr) * C + (kc) + lch);           \
        }                                                                      \
        _Pragma("unroll")                                                      \
        for (int rr = 0; rr < 2; rr++) {                                       \
            cp16(smem_u32(WH(s) + (lr + 64 * rr) * GSTR + lch),                \
                 Wh + (size_t)(bn + lr + 64 * rr) * C + (kc) + lch);           \
            cp16(smem_u32(WL(s) + (lr + 64 * rr) * GSTR + lch),                \
                 Wl + (size_t)(bn + lr + 64 * rr) * C + (kc) + lch);           \
        }                                                                      \
    } while (0)

    LOAD_STAGE(0, 0);
    CP_COMMIT();

    #pragma unroll
    for (int kk = 0; kk < 8; kk++) {
        int s = kk & 1;
        if (kk < 7) {
            LOAD_STAGE(s ^ 1, (kk + 1) * 32);
            CP_COMMIT();
            CP_WAIT(1);
        } else {
            CP_WAIT(0);
        }
        __syncthreads();

        #pragma unroll
        for (int ks = 0; ks < 2; ks++) {
            int acol = ks * 16 + (lane >> 4) * 8;
            int arow = wm + (lane & 15);
            unsigned ah[MT][4], al[MT][4];
            #pragma unroll
            for (int mt = 0; mt < MT; mt++) {
                ldmx4(ah[mt], smem_u32(XH(s) + (arow + mt * 16) * GSTR + acol));
                ldmx4(al[mt], smem_u32(XL(s) + (arow + mt * 16) * GSTR + acol));
            }
            unsigned bh[8][2], bl[8][2];
            #pragma unroll
            for (int nt4 = 0; nt4 < 4; nt4++) {
                int brow = wn + nt4 * 16 + (lane & 15);
                unsigned t[4];
                ldmx4(t, smem_u32(WH(s) + brow * GSTR + acol));
                bh[nt4 * 2][0] = t[0]; bh[nt4 * 2][1] = t[2];
                bh[nt4 * 2 + 1][0] = t[1]; bh[nt4 * 2 + 1][1] = t[3];
                ldmx4(t, smem_u32(WL(s) + brow * GSTR + acol));
                bl[nt4 * 2][0] = t[0]; bl[nt4 * 2][1] = t[2];
                bl[nt4 * 2 + 1][0] = t[1]; bl[nt4 * 2 + 1][1] = t[3];
            }
            #pragma unroll
            for (int mt = 0; mt < MT; mt++)
                #pragma unroll
                for (int nt = 0; nt < 8; nt++) {
                    mma_bf16(acc[mt][nt], ah[mt], bh[nt][0], bh[nt][1]);
                    mma_bf16(acc[mt][nt], ah[mt], bl[nt][0], bl[nt][1]);
                    mma_bf16(acc[mt][nt], al[mt], bh[nt][0], bh[nt][1]);
                }
        }
        __syncthreads();
    }

    int r_in = (lane >> 2), c_in = (lane & 3) * 2;
    #pragma unroll
    for (int mt = 0; mt < MT; mt++)
        #pragma unroll
        for (int nt = 0; nt < 8; nt++) {
            int col = bn + wn + nt * 8 + c_in;
            float b0 = bias[col], b1 = bias[col + 1];
            int row0 = bm + wm + mt * 16 + r_in;
            float s00 = (acc[mt][nt][0] + b0) * scale;
            float s01 = (acc[mt][nt][1] + b1) * scale;
            float s10 = (acc[mt][nt][2] + b0) * scale;
            float s11 = (acc[mt][nt][3] + b1) * scale;
            if (EPI == 0 || col < C) {
                size_t i0 = (size_t)row0 * C + col;
                split_store(Oh, Ol, i0, s00, s01);
                split_store(Oh, Ol, i0 + 8 * C, s10, s11);
            } else {
                size_t i0 = (size_t)row0 * C + (col - C);
                *(__nv_bfloat162*)(Ov + i0) =
                    __nv_bfloat162(__float2bfloat16(s00), __float2bfloat16(s01));
                *(__nv_bfloat162*)(Ov + i0 + 8 * C) =
                    __nv_bfloat162(__float2bfloat16(s10), __float2bfloat16(s11));
            }
        }
    #undef LOAD_STAGE
    #undef XH
    #undef XL
    #undef WH
    #undef WL
}

// ---------------- SR conv + fused x hi/lo split --------------------------------
// Block owns output pixel (oy,ox) = 4x4 input tile [oy*4..oy*4+3]x[ox*4..ox*4+3];
// those 16 values sit at window taps ky,kx in [3,6] and are split to g_xh/g_xl.
__global__ __launch_bounds__(256) void srconv_kernel(
    const float* __restrict__ x,
    const float* __restrict__ g1, const float* __restrict__ b1,
    const float* __restrict__ m1, const float* __restrict__ v1,
    const float* __restrict__ w2,
    const float* __restrict__ g2, const float* __restrict__ b2,
    const float* __restrict__ m2, const float* __restrict__ v2) {
    int opix = blockIdx.x;
    int b = blockIdx.y;
    int c = threadIdx.x;
    int oy = opix >> 4, ox = opix & 15;
    const float* xb = x + (size_t)b * NPIX * C;
    float s = 0.f;
    float own[4][4];

    if (oy >= 1 && ox >= 1) {   // interior: no bounds checks (high side never clips)
        #pragma unroll
        for (int ky = 0; ky < 7; ky++) {
            int iy = oy * 4 - 3 + ky;
            #pragma unroll
            for (int kx = 0; kx < 7; kx++) {
                int ix = ox * 4 - 3 + kx;
                float v = xb[(size_t)(iy * WIMG + ix) * C + c];
                s += v * g_w7t[(ky * 7 + kx) * C + c];
                if (ky >= 3 && kx >= 3) own[ky - 3][kx - 3] = v;
            }
        }
    } else {
        #pragma unroll
        for (int ky = 0; ky < 7; ky++) {
            int iy = oy * 4 - 3 + ky;
            #pragma unroll
            for (int kx = 0; kx < 7; kx++) {
                int ix = ox * 4 - 3 + kx;
                bool inb = (iy >= 0) && (ix >= 0);
                float v = inb ? xb[(size_t)(iy * WIMG + ix) * C + c] : 0.f;
                if (inb) s += v * g_w7t[(ky * 7 + kx) * C + c];
                if (ky >= 3 && kx >= 3) own[ky - 3][kx - 3] = v;
            }
        }
    }

    // write hi/lo split of the 16 owned input pixels (coalesced over c)
    #pragma unroll
    for (int ky2 = 0; ky2 < 4; ky2++) {
        #pragma unroll
        for (int kx2 = 0; kx2 < 4; kx2++) {
            int ip = (oy * 4 + ky2) * WIMG + ox * 4 + kx2;
            size_t idx = ((size_t)b * NPIX + ip) * C + c;
            float a = own[ky2][kx2];
            __nv_bfloat16 h = __float2bfloat16(a);
            g_xh[idx] = h;
            g_xl[idx] = __float2bfloat16(a - __bfloat162float(h));
        }
    }

    float sc1 = g1[c] * rsqrtf(v1[c] + EPS);
    float val = s * sc1 + (b1[c] - m1[c] * sc1);
    val = 0.5f * val * (1.f + erff(val * 0.7071067811865476f));
    val *= w2[c];
    float sc2 = g2[c] * rsqrtf(v2[c] + EPS);
    val = val * sc2 + (b2[c] - m2[c] * sc2);
    g_kvred[((size_t)b * MRED + opix) * C + c] = val;
}

// ---------------- local 3x3 dwconv + residual -> bf16 hi/lo -------------------
__global__ __launch_bounds__(128) void localconv_kernel(
    const float* __restrict__ lb) {
    int opix = blockIdx.x;
    int b = blockIdx.y;
    int c = threadIdx.x * 2;
    int y = opix >> 4, xq = opix & 15;
    const float* src = g_kvred + (size_t)b * MRED * C;
    float2 ctr = *(const float2*)(src + (size_t)opix * C + c);
    float s0 = lb[c] + ctr.x;
    float s1 = lb[c + 1] + ctr.y;
    #pragma unroll
    for (int dy = -1; dy <= 1; dy++) {
        int yy = y + dy;
        if (yy < 0 || yy >= 16) continue;
        #pragma unroll
        for (int dx = -1; dx <= 1; dx++) {
            int xx = xq + dx;
            if (xx < 0 || xx >= 16) continue;
            float2 wv = *(const float2*)(g_lwt + ((dy + 1) * 3 + (dx + 1)) * C + c);
            float2 sv = *(const float2*)(src + (size_t)(yy * 16 + xx) * C + c);
            s0 += sv.x * wv.x;
            s1 += sv.y * wv.y;
        }
    }
    split_store(g_kv2h, g_kv2l, ((size_t)b * MRED + opix) * C + c, s0, s1);
}

// ---------------- flash attention via mma.sync bf16 ---------------------------
// smem: K hi/lo [256][QSTR] + Vt [32][VSTR]; Q fragments loaded from gmem.
#define QSTR 40
#define VSTR 264
#define SM_KHI 0
#define SM_KLO (SM_KHI + 256 * QSTR)
#define SM_VT  (SM_KLO + 256 * QSTR)
#define ATTN_SMEM ((SM_VT + 32 * VSTR) * 2)

__global__ __launch_bounds__(256, 2) void attn_kernel(float* __restrict__ out) {
    extern __shared__ __nv_bfloat16 sm[];
    __nv_bfloat16* khi = sm + SM_KHI;
    __nv_bfloat16* klo = sm + SM_KLO;
    __nv_bfloat16* vt  = sm + SM_VT;

    int tid = threadIdx.x, lane = tid & 31, w = tid >> 5;
    int qt = blockIdx.x, head = blockIdx.y, b = blockIdx.z;

    // ---- stage K (hi/lo bf16 direct copy) and V transposed ----
    for (int i = tid; i < 1024; i += 256) {
        int m = i >> 2, ch = (i & 3) * 8;
        size_t src = (size_t)(b * MRED + m) * C + head * HD + ch;
        *(uint4*)(khi + m * QSTR + ch) = *(const uint4*)(g_kh + src);
        *(uint4*)(klo + m * QSTR + ch) = *(const uint4*)(g_kl + src);
    }
    for (int i = tid; i < 256 * 16; i += 256) {
        int m = i >> 4, d2 = (i & 15) * 2;
        __nv_bfloat162 v = *(const __nv_bfloat162*)(
            g_v + (size_t)(b * MRED + m) * C + head * HD + d2);
        vt[d2 * VSTR + m] = v.x;
        vt[(d2 + 1) * VSTR + m] = v.y;
    }

    // ---- load Q fragments directly from gmem (pre-scaled hi/lo) ----
    int m0 = w * 16;
    unsigned qh[2][4], ql[2][4];
    {
        size_t qbase = (size_t)(b * NPIX + qt * 128 + m0 + (lane >> 2)) * C
                       + head * HD + (lane & 3) * 2;
        #pragma unroll
        for (int kt = 0; kt < 2; kt++) {
            size_t o0 = qbase + kt * 16;
            qh[kt][0] = *(const unsigned*)(g_qh + o0);
            qh[kt][1] = *(const unsigned*)(g_qh + o0 + 8 * C);
            qh[kt][2] = *(const unsigned*)(g_qh + o0 + 8);
            qh[kt][3] = *(const unsigned*)(g_qh + o0 + 8 * C + 8);
            ql[kt][0] = *(const unsigned*)(g_ql + o0);
            ql[kt][1] = *(const unsigned*)(g_ql + o0 + 8 * C);
            ql[kt][2] = *(const unsigned*)(g_ql + o0 + 8);
            ql[kt][3] = *(const unsigned*)(g_ql + o0 + 8 * C + 8);
        }
    }
    __syncthreads();

    float m_lo = -1e30f, m_hi = -1e30f, sum_lo = 0.f, sum_hi = 0.f;
    float o[4][4];
    #pragma unroll
    for (int i = 0; i < 4; i++)
        #pragma unroll
        for (int j = 0; j < 4; j++) o[i][j] = 0.f;

    #pragma unroll
    for (int kb = 0; kb < 4; kb++) {
        float s[8][4];
        #pragma unroll
        for (int j = 0; j < 8; j++)
            #pragma unroll
            for (int q = 0; q < 4; q++) s[j][q] = 0.f;
        #pragma unroll
        for (int kt = 0; kt < 2; kt++) {
            int col = kt * 16 + (lane >> 4) * 8;
            #pragma unroll
            for (int jj = 0; jj < 4; jj++) {
                int row = kb * 64 + jj * 16 + (lane & 15);
                unsigned th[4], tl[4];
                ldmx4(th, smem_u32(khi + row * QSTR + col));
                ldmx4(tl, smem_u32(klo + row * QSTR + col));
                mma_bf16(s[2 * jj], qh[kt], th[0], th[2]);
                mma_bf16(s[2 * jj], qh[kt], tl[0], tl[2]);
                mma_bf16(s[2 * jj], ql[kt], th[0], th[2]);
                mma_bf16(s[2 * jj + 1], qh[kt], th[1], th[3]);
                mma_bf16(s[2 * jj + 1], qh[kt], tl[1], tl[3]);
                mma_bf16(s[2 * jj + 1], ql[kt], th[1], th[3]);
            }
        }
        float bm_lo = -1e30f, bm_hi = -1e30f;
        #pragma unroll
        for (int j = 0; j < 8; j++) {
            bm_lo = fmaxf(bm_lo, fmaxf(s[j][0], s[j][1]));
            bm_hi = fmaxf(bm_hi, fmaxf(s[j][2], s[j][3]));
        }
        bm_lo = fmaxf(bm_lo, __shfl_xor_sync(0xFFFFFFFFu, bm_lo, 1));
        bm_lo = fmaxf(bm_lo, __shfl_xor_sync(0xFFFFFFFFu, bm_lo, 2));
        bm_hi = fmaxf(bm_hi, __shfl_xor_sync(0xFFFFFFFFu, bm_hi, 1));
        bm_hi = fmaxf(bm_hi, __shfl_xor_sync(0xFFFFFFFFu, bm_hi, 2));
        float nm_lo = fmaxf(m_lo, bm_lo);
        float nm_hi = fmaxf(m_hi, bm_hi);
        float corr_lo = exp2f(m_lo - nm_lo);
        float corr_hi = exp2f(m_hi - nm_hi);
        m_lo = nm_lo; m_hi = nm_hi;
        sum_lo *= corr_lo; sum_hi *= corr_hi;
        #pragma unroll
        for (int dn = 0; dn < 4; dn++) {
            o[dn][0] *= corr_lo; o[dn][1] *= corr_lo;
            o[dn][2] *= corr_hi; o[dn][3] *= corr_hi;
        }
        unsigned pl[8], ph[8];
        #pragma unroll
        for (int j = 0; j < 8; j++) {
            float p0 = exp2f(s[j][0] - m_lo);
            float p1 = exp2f(s[j][1] - m_lo);
            float p2 = exp2f(s[j][2] - m_hi);
            float p3 = exp2f(s[j][3] - m_hi);
            sum_lo += p0 + p1;
            sum_hi += p2 + p3;
            pl[j] = pack_bf16x2(p0, p1);
            ph[j] = pack_bf16x2(p2, p3);
        }
        #pragma unroll
        for (int kt = 0; kt < 4; kt++) {
            unsigned a[4] = {pl[2 * kt], ph[2 * kt], pl[2 * kt + 1], ph[2 * kt + 1]};
            int kcol = kb * 64 + kt * 16 + (lane >> 4) * 8;
            #pragma unroll
            for (int dn2 = 0; dn2 < 2; dn2++) {
                int drow = dn2 * 16 + (lane & 15);
                unsigned t[4];
                ldmx4(t, smem_u32(vt + drow * VSTR + kcol));
                mma_bf16(o[2 * dn2], a, t[0], t[2]);
                mma_bf16(o[2 * dn2 + 1], a, t[1], t[3]);
            }
        }
    }

    sum_lo += __shfl_xor_sync(0xFFFFFFFFu, sum_lo, 1);
    sum_lo += __shfl_xor_sync(0xFFFFFFFFu, sum_lo, 2);
    sum_hi += __shfl_xor_sync(0xFFFFFFFFu, sum_hi, 1);
    sum_hi += __shfl_xor_sync(0xFFFFFFFFu, sum_hi, 2);
    float inv_lo = 1.f / sum_lo;
    float inv_hi = 1.f / sum_hi;
    int r = lane >> 2, cc = (lane & 3) * 2;
    int q0 = qt * 128 + m0 + r;
    #pragma unroll
    for (int dn = 0; dn < 4; dn++) {
        int d = dn * 8 + cc;
        float2 t0 = make_float2(o[dn][0] * inv_lo, o[dn][1] * inv_lo);
        float2 t1 = make_float2(o[dn][2] * inv_hi, o[dn][3] * inv_hi);
        *(float2*)(out + ((size_t)(b * NPIX + q0)) * C + head * HD + d) = t0;
        *(float2*)(out + ((size_t)(b * NPIX + q0 + 8)) * C + head * HD + d) = t1;
    }
}

// ---------------- launch ------------------------------------------------------
extern "C" void kernel_launch(void* const* d_in, const int* in_sizes, int n_in,
                              void* d_out, int out_size) {
    int base = (n_in >= 19) ? 3 : 1;
    const float* x      = (const float*)d_in[0];
    const float* Wq     = (const float*)d_in[base + 0];
    const float* bq     = (const float*)d_in[base + 1];
    const float* Wkv    = (const float*)d_in[base + 2];
    const float* bkv    = (const float*)d_in[base + 3];
    const float* sr_w1  = (const float*)d_in[base + 4];
    const float* bn1g   = (const float*)d_in[base + 5];
    const float* bn1b   = (const float*)d_in[base + 6];
    const float* bn1m   = (const float*)d_in[base + 7];
    const float* bn1v   = (const float*)d_in[base + 8];
    const float* sr_w2  = (const float*)d_in[base + 9];
    const float* bn2g   = (const float*)d_in[base + 10];
    const float* bn2b   = (const float*)d_in[base + 11];
    const float* bn2m   = (const float*)d_in[base + 12];
    const float* bn2v   = (const float*)d_in[base + 13];
    const float* lw     = (const float*)d_in[base + 14];
    const float* lb     = (const float*)d_in[base + 15];
    float* out = (float*)d_out;

    __nv_bfloat16 *xh, *xl, *wqh, *wql, *wkvh, *wkvl, *kv2h, *kv2l;
    __nv_bfloat16 *qh, *ql, *kh, *kl, *vv;
    cudaGetSymbolAddress((void**)&xh, g_xh);
    cudaGetSymbolAddress((void**)&xl, g_xl);
    cudaGetSymbolAddress((void**)&wqh, g_wqh);
    cudaGetSymbolAddress((void**)&wql, g_wql);
    cudaGetSymbolAddress((void**)&wkvh, g_wkvh);
    cudaGetSymbolAddress((void**)&wkvl, g_wkvl);
    cudaGetSymbolAddress((void**)&kv2h, g_kv2h);
    cudaGetSymbolAddress((void**)&kv2l, g_kv2l);
    cudaGetSymbolAddress((void**)&qh, g_qh);
    cudaGetSymbolAddress((void**)&ql, g_ql);
    cudaGetSymbolAddress((void**)&kh, g_kh);
    cudaGetSymbolAddress((void**)&kl, g_kl);
    cudaGetSymbolAddress((void**)&vv, g_v);

    const int smem128 = 2 * (2 * 128 * GSTR + 2 * 128 * GSTR) * 2;  // 81920
    const int smem64  = 2 * (2 * 64 * GSTR + 2 * 128 * GSTR) * 2;   // 61440
    cudaFuncSetAttribute((const void*)gemm_mma_kernel<128, 0>,
                         cudaFuncAttributeMaxDynamicSharedMemorySize, smem128);
    cudaFuncSetAttribute((const void*)gemm_mma_kernel<64, 1>,
                         cudaFuncAttributeMaxDynamicSharedMemorySize, smem64);
    cudaFuncSetAttribute((const void*)attn_kernel,
                         cudaFuncAttributeMaxDynamicSharedMemorySize, ATTN_SMEM);

    const float QSC = ATTN_SCALE * 1.4426950408889634f;

    prep_weights_kernel<<<192 + 49, 256>>>(Wq, Wkv, sr_w1, lw);
    // srconv also produces g_xh/g_xl (fused x split)
    srconv_kernel<<<dim3(MRED, BATCH), 256>>>(x, bn1g, bn1b, bn1m, bn1v,
                                              sr_w2, bn2g, bn2b, bn2m, bn2v);
    localconv_kernel<<<dim3(MRED, BATCH), 128>>>(lb);
    gemm_mma_kernel<64, 1><<<dim3(BATCH * MRED / 64, 2 * C / 128), 256, smem64>>>(
        kv2h, kv2l, wkvh, wkvl, bkv, kh, kl, vv, 1.0f);
    gemm_mma_kernel<128, 0><<<dim3(BATCH * NPIX / 128, C / 128), 256, smem128>>>(
        xh, xl, wqh, wql, bq, qh, ql, nullptr, QSC);
    attn_kernel<<<dim3(NPIX / 128, HEADS, BATCH), 256, ATTN_SMEM>>>(out);
}

// round 12
// speedup vs baseline: 1.1583x; 1.1583x over previous
#include <cuda_runtime.h>
#include <cuda_bf16.h>
#include <math.h>
#include <string.h>

#define BATCH 8
#define C 256
#define NPIX 4096
#define HIMG 64
#define WIMG 64
#define MRED 256
#define HEADS 8
#define HD 32
#define ATTN_SCALE 0.17677669529663687f
#define EPS 1e-5f

// ---------------- scratch ----------------------------------------------------
__device__ float g_kvred[BATCH * MRED * C];   // (b, m, c)
// pre-split bf16 operands
__device__ __nv_bfloat16 g_xh[BATCH * NPIX * C], g_xl[BATCH * NPIX * C];
__device__ __nv_bfloat16 g_wqh[C * C], g_wql[C * C];
__device__ __nv_bfloat16 g_wkvh[2 * C * C], g_wkvl[2 * C * C];
__device__ __nv_bfloat16 g_kv2h[BATCH * MRED * C], g_kv2l[BATCH * MRED * C];
// q projection, pre-scaled hi/lo bf16 (b*n, c)
__device__ __nv_bfloat16 g_qh[BATCH * NPIX * C], g_ql[BATCH * NPIX * C];
// kv projection: K hi/lo split + V bf16, all (b, m, c)
__device__ __nv_bfloat16 g_kh[BATCH * MRED * C], g_kl[BATCH * MRED * C];
__device__ __nv_bfloat16 g_v[BATCH * MRED * C];
// transposed conv weights [k][c]
__device__ float g_w7t[49 * C];
__device__ float g_lwt[9 * C];

// ---------------- helpers ------------------------------------------------------
__device__ __forceinline__ unsigned smem_u32(const void* p) {
    unsigned a;
    asm("{ .reg .u64 t; cvta.to.shared.u64 t, %1; cvt.u32.u64 %0, t; }"
        : "=r"(a) : "l"(p));
    return a;
}
__device__ __forceinline__ void cp16(unsigned dst, const void* src) {
    asm volatile("cp.async.ca.shared.global [%0], [%1], 16;"
                 :: "r"(dst), "l"(src));
}
#define CP_COMMIT() asm volatile("cp.async.commit_group;" ::: "memory")
#define CP_WAIT(n)  asm volatile("cp.async.wait_group %0;" :: "n"(n) : "memory")

__device__ __forceinline__ void ldmx4(unsigned* r, unsigned addr) {
    asm volatile("ldmatrix.sync.aligned.m8n8.x4.shared.b16 {%0,%1,%2,%3}, [%4];"
                 : "=r"(r[0]), "=r"(r[1]), "=r"(r[2]), "=r"(r[3]) : "r"(addr));
}
__device__ __forceinline__ void mma_bf16(float* c, const unsigned* a,
                                         unsigned b0, unsigned b1) {
    asm volatile(
        "mma.sync.aligned.m16n8k16.row.col.f32.bf16.bf16.f32 "
        "{%0,%1,%2,%3}, {%4,%5,%6,%7}, {%8,%9}, {%0,%1,%2,%3};"
        : "+f"(c[0]), "+f"(c[1]), "+f"(c[2]), "+f"(c[3])
        : "r"(a[0]), "r"(a[1]), "r"(a[2]), "r"(a[3]), "r"(b0), "r"(b1));
}
__device__ __forceinline__ unsigned pack_bf16x2(float lo, float hi) {
    unsigned d;
    asm("cvt.rn.bf16x2.f32 %0, %1, %2;" : "=r"(d) : "f"(hi), "f"(lo));
    return d;
}
__device__ __forceinline__ void split_store(__nv_bfloat16* hi, __nv_bfloat16* lo,
                                            size_t idx, float a0, float a1) {
    __nv_bfloat16 h0 = __float2bfloat16(a0);
    __nv_bfloat16 h1 = __float2bfloat16(a1);
    *(__nv_bfloat162*)(hi + idx) = __nv_bfloat162(h0, h1);
    *(__nv_bfloat162*)(lo + idx) = __nv_bfloat162(
        __float2bfloat16(a0 - __bfloat162float(h0)),
        __float2bfloat16(a1 - __bfloat162float(h1)));
}

// ---------------- fp32 -> bf16 hi/lo split (x) --------------------------------
__global__ __launch_bounds__(256) void split_kernel(
    const float* __restrict__ src, __nv_bfloat16* __restrict__ hi,
    __nv_bfloat16* __restrict__ lo, int n4) {
    int i = blockIdx.x * 256 + threadIdx.x;
    if (i >= n4) return;
    float4 v = ((const float4*)src)[i];
    split_store(hi, lo, 4 * (size_t)i, v.x, v.y);
    split_store(hi, lo, 4 * (size_t)i + 2, v.z, v.w);
}

// ---------------- weights prep: Wq/Wkv split + conv-weight transpose ----------
__global__ __launch_bounds__(256) void prep_weights_kernel(
    const float* __restrict__ Wq, const float* __restrict__ Wkv,
    const float* __restrict__ w7, const float* __restrict__ lw) {
    int bx = blockIdx.x, tid = threadIdx.x;
    if (bx < 64) {                       // Wq: 16384 float4
        int i = bx * 256 + tid;
        float4 v = ((const float4*)Wq)[i];
        split_store(g_wqh, g_wql, 4 * (size_t)i, v.x, v.y);
        split_store(g_wqh, g_wql, 4 * (size_t)i + 2, v.z, v.w);
    } else if (bx < 192) {               // Wkv: 32768 float4
        int i = (bx - 64) * 256 + tid;
        float4 v = ((const float4*)Wkv)[i];
        split_store(g_wkvh, g_wkvl, 4 * (size_t)i, v.x, v.y);
        split_store(g_wkvh, g_wkvl, 4 * (size_t)i + 2, v.z, v.w);
    } else {                             // conv weight transpose, k = bx-192
        int k = bx - 192;
        g_w7t[k * C + tid] = w7[tid * 49 + k];
        if (k < 9) g_lwt[k * C + tid] = lw[tid * 9 + k];
    }
}

// ---------------- HMMA GEMM, bf16-split inputs + cp.async double buffer -------
// EPI 0: q-style (scale then hi/lo split out). EPI 1: kv-style (K split, V bf16).
#define GSTR 40
template <int BM, int EPI>
__global__ __launch_bounds__(256, 2) void gemm_mma_kernel(
    const __nv_bfloat16* __restrict__ Xh, const __nv_bfloat16* __restrict__ Xl,
    const __nv_bfloat16* __restrict__ Wh, const __nv_bfloat16* __restrict__ Wl,
    const float* __restrict__ bias,
    __nv_bfloat16* __restrict__ Oh, __nv_bfloat16* __restrict__ Ol,
    __nv_bfloat16* __restrict__ Ov, float scale) {
    constexpr int MT = BM / 64;
    constexpr int SX = BM * GSTR;
    constexpr int SW = 128 * GSTR;
    constexpr int STG = 2 * SX + 2 * SW;
    extern __shared__ __nv_bfloat16 gsm[];

    int tid = threadIdx.x, lane = tid & 31, w = tid >> 5;
    int bm = blockIdx.x * BM, bn = blockIdx.y * 128;
    int wm = (w & 3) * (16 * MT), wn = (w >> 2) * 64;
    int lr = tid >> 2, lch = (tid & 3) * 8;

    float acc[MT][8][4];
    #pragma unroll
    for (int mt = 0; mt < MT; mt++)
        #pragma unroll
        for (int nt = 0; nt < 8; nt++)
            #pragma unroll
            for (int q = 0; q < 4; q++) acc[mt][nt][q] = 0.f;

    #define XH(s) (gsm + (s) * STG)
    #define XL(s) (gsm + (s) * STG + SX)
    #define WH(s) (gsm + (s) * STG + 2 * SX)
    #define WL(s) (gsm + (s) * STG + 2 * SX + SW)

    #define LOAD_STAGE(s, kc) do {                                            \
        _Pragma("unroll")                                                      \
        for (int rr = 0; rr < MT; rr++) {                                      \
            cp16(smem_u32(XH(s) + (lr + 64 * rr) * GSTR + lch),                \
                 Xh + (size_t)(bm + lr + 64 * rr) * C + (kc) + lch);           \
            cp16(smem_u32(XL(s) + (lr + 64 * rr) * GSTR + lch),                \
                 Xl + (size_t)(bm + lr + 64 * rr) * C + (kc) + lch);           \
        }                                                                      \
        _Pragma("unroll")                                                      \
        for (int rr = 0; rr < 2; rr++) {                                       \
            cp16(smem_u32(WH(s) + (lr + 64 * rr) * GSTR + lch),                \
                 Wh + (size_t)(bn + lr + 64 * rr) * C + (kc) + lch);           \
            cp16(smem_u32(WL(s) + (lr + 64 * rr) * GSTR + lch),                \
                 Wl + (size_t)(bn + lr + 64 * rr) * C + (kc) + lch);           \
        }                                                                      \
    } while (0)

    LOAD_STAGE(0, 0);
    CP_COMMIT();

    #pragma unroll
    for (int kk = 0; kk < 8; kk++) {
        int s = kk & 1;
        if (kk < 7) {
            LOAD_STAGE(s ^ 1, (kk + 1) * 32);
            CP_COMMIT();
            CP_WAIT(1);
        } else {
            CP_WAIT(0);
        }
        __syncthreads();

        #pragma unroll
        for (int ks = 0; ks < 2; ks++) {
            int acol = ks * 16 + (lane >> 4) * 8;
            int arow = wm + (lane & 15);
            unsigned ah[MT][4], al[MT][4];
            #pragma unroll
            for (int mt = 0; mt < MT; mt++) {
                ldmx4(ah[mt], smem_u32(XH(s) + (arow + mt * 16) * GSTR + acol));
                ldmx4(al[mt], smem_u32(XL(s) + (arow + mt * 16) * GSTR + acol));
            }
            unsigned bh[8][2], bl[8][2];
            #pragma unroll
            for (int nt4 = 0; nt4 < 4; nt4++) {
                int brow = wn + nt4 * 16 + (lane & 15);
                unsigned t[4];
                ldmx4(t, smem_u32(WH(s) + brow * GSTR + acol));
                bh[nt4 * 2][0] = t[0]; bh[nt4 * 2][1] = t[2];
                bh[nt4 * 2 + 1][0] = t[1]; bh[nt4 * 2 + 1][1] = t[3];
                ldmx4(t, smem_u32(WL(s) + brow * GSTR + acol));
                bl[nt4 * 2][0] = t[0]; bl[nt4 * 2][1] = t[2];
                bl[nt4 * 2 + 1][0] = t[1]; bl[nt4 * 2 + 1][1] = t[3];
            }
            #pragma unroll
            for (int mt = 0; mt < MT; mt++)
                #pragma unroll
                for (int nt = 0; nt < 8; nt++) {
                    mma_bf16(acc[mt][nt], ah[mt], bh[nt][0], bh[nt][1]);
                    mma_bf16(acc[mt][nt], ah[mt], bl[nt][0], bl[nt][1]);
                    mma_bf16(acc[mt][nt], al[mt], bh[nt][0], bh[nt][1]);
                }
        }
        __syncthreads();
    }

    int r_in = (lane >> 2), c_in = (lane & 3) * 2;
    #pragma unroll
    for (int mt = 0; mt < MT; mt++)
        #pragma unroll
        for (int nt = 0; nt < 8; nt++) {
            int col = bn + wn + nt * 8 + c_in;
            float b0 = bias[col], b1 = bias[col + 1];
            int row0 = bm + wm + mt * 16 + r_in;
            float s00 = (acc[mt][nt][0] + b0) * scale;
            float s01 = (acc[mt][nt][1] + b1) * scale;
            float s10 = (acc[mt][nt][2] + b0) * scale;
            float s11 = (acc[mt][nt][3] + b1) * scale;
            if (EPI == 0 || col < C) {
                size_t i0 = (size_t)row0 * C + col;
                split_store(Oh, Ol, i0, s00, s01);
                split_store(Oh, Ol, i0 + 8 * C, s10, s11);
            } else {
                size_t i0 = (size_t)row0 * C + (col - C);
                *(__nv_bfloat162*)(Ov + i0) =
                    __nv_bfloat162(__float2bfloat16(s00), __float2bfloat16(s01));
                *(__nv_bfloat162*)(Ov + i0 + 8 * C) =
                    __nv_bfloat162(__float2bfloat16(s10), __float2bfloat16(s11));
            }
        }
    #undef LOAD_STAGE
    #undef XH
    #undef XL
    #undef WH
    #undef WL
}

// ---------------- SR conv (transposed weights) --------------------------------
__global__ __launch_bounds__(256) void srconv_kernel(
    const float* __restrict__ x,
    const float* __restrict__ g1, const float* __restrict__ b1,
    const float* __restrict__ m1, const float* __restrict__ v1,
    const float* __restrict__ w2,
    const float* __restrict__ g2, const float* __restrict__ b2,
    const float* __restrict__ m2, const float* __restrict__ v2) {
    int opix = blockIdx.x;
    int b = blockIdx.y;
    int c = threadIdx.x;
    int oy = opix >> 4, ox = opix & 15;
    const float* xb = x + (size_t)b * NPIX * C;
    float s = 0.f;
    #pragma unroll
    for (int ky = 0; ky < 7; ky++) {
        int iy = oy * 4 - 3 + ky;
        if (iy < 0 || iy >= HIMG) continue;
        #pragma unroll
        for (int kx = 0; kx < 7; kx++) {
            int ix = ox * 4 - 3 + kx;
            if (ix < 0 || ix >= WIMG) continue;
            s += xb[(size_t)(iy * WIMG + ix) * C + c] * g_w7t[(ky * 7 + kx) * C + c];
        }
    }
    float sc1 = g1[c] * rsqrtf(v1[c] + EPS);
    float val = s * sc1 + (b1[c] - m1[c] * sc1);
    val = 0.5f * val * (1.f + erff(val * 0.7071067811865476f));
    val *= w2[c];
    float sc2 = g2[c] * rsqrtf(v2[c] + EPS);
    val = val * sc2 + (b2[c] - m2[c] * sc2);
    g_kvred[((size_t)b * MRED + opix) * C + c] = val;
}

// ---------------- local 3x3 dwconv + residual -> bf16 hi/lo -------------------
__global__ __launch_bounds__(128) void localconv_kernel(
    const float* __restrict__ lb) {
    int opix = blockIdx.x;
    int b = blockIdx.y;
    int c = threadIdx.x * 2;
    int y = opix >> 4, xq = opix & 15;
    const float* src = g_kvred + (size_t)b * MRED * C;
    float2 ctr = *(const float2*)(src + (size_t)opix * C + c);
    float s0 = lb[c] + ctr.x;
    float s1 = lb[c + 1] + ctr.y;
    #pragma unroll
    for (int dy = -1; dy <= 1; dy++) {
        int yy = y + dy;
        if (yy < 0 || yy >= 16) continue;
        #pragma unroll
        for (int dx = -1; dx <= 1; dx++) {
            int xx = xq + dx;
            if (xx < 0 || xx >= 16) continue;
            float2 wv = *(const float2*)(g_lwt + ((dy + 1) * 3 + (dx + 1)) * C + c);
            float2 sv = *(const float2*)(src + (size_t)(yy * 16 + xx) * C + c);
            s0 += sv.x * wv.x;
            s1 += sv.y * wv.y;
        }
    }
    split_store(g_kv2h, g_kv2l, ((size_t)b * MRED + opix) * C + c, s0, s1);
}

// ---------------- flash attention via mma.sync bf16 ---------------------------
// Block stages K/V once, then processes 2 q-tiles (256 queries) sequentially.
#define QSTR 40
#define VSTR 264
#define SM_KHI 0
#define SM_KLO (SM_KHI + 256 * QSTR)
#define SM_VT  (SM_KLO + 256 * QSTR)
#define ATTN_SMEM ((SM_VT + 32 * VSTR) * 2)

__global__ __launch_bounds__(256, 2) void attn_kernel(float* __restrict__ out) {
    extern __shared__ __nv_bfloat16 sm[];
    __nv_bfloat16* khi = sm + SM_KHI;
    __nv_bfloat16* klo = sm + SM_KLO;
    __nv_bfloat16* vt  = sm + SM_VT;

    int tid = threadIdx.x, lane = tid & 31, w = tid >> 5;
    int head = blockIdx.y, b = blockIdx.z;

    // ---- stage K (hi/lo bf16 direct copy) and V transposed ----
    for (int i = tid; i < 1024; i += 256) {
        int m = i >> 2, ch = (i & 3) * 8;
        size_t src = (size_t)(b * MRED + m) * C + head * HD + ch;
        *(uint4*)(khi + m * QSTR + ch) = *(const uint4*)(g_kh + src);
        *(uint4*)(klo + m * QSTR + ch) = *(const uint4*)(g_kl + src);
    }
    for (int i = tid; i < 256 * 16; i += 256) {
        int m = i >> 4, d2 = (i & 15) * 2;
        __nv_bfloat162 v = *(const __nv_bfloat162*)(
            g_v + (size_t)(b * MRED + m) * C + head * HD + d2);
        vt[d2 * VSTR + m] = v.x;
        vt[(d2 + 1) * VSTR + m] = v.y;
    }
    __syncthreads();

    int m0 = w * 16;

    #pragma unroll 1
    for (int qq = 0; qq < 2; qq++) {
        int qtile = blockIdx.x * 2 + qq;

        // ---- load Q fragments directly from gmem (pre-scaled hi/lo) ----
        unsigned qh[2][4], ql[2][4];
        {
            size_t qbase = (size_t)(b * NPIX + qtile * 128 + m0 + (lane >> 2)) * C
                           + head * HD + (lane & 3) * 2;
            #pragma unroll
            for (int kt = 0; kt < 2; kt++) {
                size_t o0 = qbase + kt * 16;
                qh[kt][0] = *(const unsigned*)(g_qh + o0);
                qh[kt][1] = *(const unsigned*)(g_qh + o0 + 8 * C);
                qh[kt][2] = *(const unsigned*)(g_qh + o0 + 8);
                qh[kt][3] = *(const unsigned*)(g_qh + o0 + 8 * C + 8);
                ql[kt][0] = *(const unsigned*)(g_ql + o0);
                ql[kt][1] = *(const unsigned*)(g_ql + o0 + 8 * C);
                ql[kt][2] = *(const unsigned*)(g_ql + o0 + 8);
                ql[kt][3] = *(const unsigned*)(g_ql + o0 + 8 * C + 8);
            }
        }

        float m_lo = -1e30f, m_hi = -1e30f, sum_lo = 0.f, sum_hi = 0.f;
        float o[4][4];
        #pragma unroll
        for (int i = 0; i < 4; i++)
            #pragma unroll
            for (int j = 0; j < 4; j++) o[i][j] = 0.f;

        #pragma unroll
        for (int kb = 0; kb < 4; kb++) {
            float s[8][4];
            #pragma unroll
            for (int j = 0; j < 8; j++)
                #pragma unroll
                for (int q = 0; q < 4; q++) s[j][q] = 0.f;
            #pragma unroll
            for (int kt = 0; kt < 2; kt++) {
                int col = kt * 16 + (lane >> 4) * 8;
                #pragma unroll
                for (int jj = 0; jj < 4; jj++) {
                    int row = kb * 64 + jj * 16 + (lane & 15);
                    unsigned th[4], tl[4];
                    ldmx4(th, smem_u32(khi + row * QSTR + col));
                    ldmx4(tl, smem_u32(klo + row * QSTR + col));
                    mma_bf16(s[2 * jj], qh[kt], th[0], th[2]);
                    mma_bf16(s[2 * jj], qh[kt], tl[0], tl[2]);
                    mma_bf16(s[2 * jj], ql[kt], th[0], th[2]);
                    mma_bf16(s[2 * jj + 1], qh[kt], th[1], th[3]);
                    mma_bf16(s[2 * jj + 1], qh[kt], tl[1], tl[3]);
                    mma_bf16(s[2 * jj + 1], ql[kt], th[1], th[3]);
                }
            }
            float bm_lo = -1e30f, bm_hi = -1e30f;
            #pragma unroll
            for (int j = 0; j < 8; j++) {
                bm_lo = fmaxf(bm_lo, fmaxf(s[j][0], s[j][1]));
                bm_hi = fmaxf(bm_hi, fmaxf(s[j][2], s[j][3]));
            }
            bm_lo = fmaxf(bm_lo, __shfl_xor_sync(0xFFFFFFFFu, bm_lo, 1));
            bm_lo = fmaxf(bm_lo, __shfl_xor_sync(0xFFFFFFFFu, bm_lo, 2));
            bm_hi = fmaxf(bm_hi, __shfl_xor_sync(0xFFFFFFFFu, bm_hi, 1));
            bm_hi = fmaxf(bm_hi, __shfl_xor_sync(0xFFFFFFFFu, bm_hi, 2));
            float nm_lo = fmaxf(m_lo, bm_lo);
            float nm_hi = fmaxf(m_hi, bm_hi);
            float corr_lo = exp2f(m_lo - nm_lo);
            float corr_hi = exp2f(m_hi - nm_hi);
            m_lo = nm_lo; m_hi = nm_hi;
            sum_lo *= corr_lo; sum_hi *= corr_hi;
            #pragma unroll
            for (int dn = 0; dn < 4; dn++) {
                o[dn][0] *= corr_lo; o[dn][1] *= corr_lo;
                o[dn][2] *= corr_hi; o[dn][3] *= corr_hi;
            }
            unsigned pl[8], ph[8];
            #pragma unroll
            for (int j = 0; j < 8; j++) {
                float p0 = exp2f(s[j][0] - m_lo);
                float p1 = exp2f(s[j][1] - m_lo);
                float p2 = exp2f(s[j][2] - m_hi);
                float p3 = exp2f(s[j][3] - m_hi);
                sum_lo += p0 + p1;
                sum_hi += p2 + p3;
                pl[j] = pack_bf16x2(p0, p1);
                ph[j] = pack_bf16x2(p2, p3);
            }
            #pragma unroll
            for (int kt = 0; kt < 4; kt++) {
                unsigned a[4] = {pl[2 * kt], ph[2 * kt],
                                 pl[2 * kt + 1], ph[2 * kt + 1]};
                int kcol = kb * 64 + kt * 16 + (lane >> 4) * 8;
                #pragma unroll
                for (int dn2 = 0; dn2 < 2; dn2++) {
                    int drow = dn2 * 16 + (lane & 15);
                    unsigned t[4];
                    ldmx4(t, smem_u32(vt + drow * VSTR + kcol));
                    mma_bf16(o[2 * dn2], a, t[0], t[2]);
                    mma_bf16(o[2 * dn2 + 1], a, t[1], t[3]);
                }
            }
        }

        sum_lo += __shfl_xor_sync(0xFFFFFFFFu, sum_lo, 1);
        sum_lo += __shfl_xor_sync(0xFFFFFFFFu, sum_lo, 2);
        sum_hi += __shfl_xor_sync(0xFFFFFFFFu, sum_hi, 1);
        sum_hi += __shfl_xor_sync(0xFFFFFFFFu, sum_hi, 2);
        float inv_lo = 1.f / sum_lo;
        float inv_hi = 1.f / sum_hi;
        int r = lane >> 2, cc = (lane & 3) * 2;
        int q0 = qtile * 128 + m0 + r;
        #pragma unroll
        for (int dn = 0; dn < 4; dn++) {
            int d = dn * 8 + cc;
            float2 t0 = make_float2(o[dn][0] * inv_lo, o[dn][1] * inv_lo);
            float2 t1 = make_float2(o[dn][2] * inv_hi, o[dn][3] * inv_hi);
            *(float2*)(out + ((size_t)(b * NPIX + q0)) * C + head * HD + d) = t0;
            *(float2*)(out + ((size_t)(b * NPIX + q0 + 8)) * C + head * HD + d) = t1;
        }
    }
}

// ---------------- launch ------------------------------------------------------
extern "C" void kernel_launch(void* const* d_in, const int* in_sizes, int n_in,
                              void* d_out, int out_size) {
    int base = (n_in >= 19) ? 3 : 1;
    const float* x      = (const float*)d_in[0];
    const float* Wq     = (const float*)d_in[base + 0];
    const float* bq     = (const float*)d_in[base + 1];
    const float* Wkv    = (const float*)d_in[base + 2];
    const float* bkv    = (const float*)d_in[base + 3];
    const float* sr_w1  = (const float*)d_in[base + 4];
    const float* bn1g   = (const float*)d_in[base + 5];
    const float* bn1b   = (const float*)d_in[base + 6];
    const float* bn1m   = (const float*)d_in[base + 7];
    const float* bn1v   = (const float*)d_in[base + 8];
    const float* sr_w2  = (const float*)d_in[base + 9];
    const float* bn2g   = (const float*)d_in[base + 10];
    const float* bn2b   = (const float*)d_in[base + 11];
    const float* bn2m   = (const float*)d_in[base + 12];
    const float* bn2v   = (const float*)d_in[base + 13];
    const float* lw     = (const float*)d_in[base + 14];
    const float* lb     = (const float*)d_in[base + 15];
    float* out = (float*)d_out;

    __nv_bfloat16 *xh, *xl, *wqh, *wql, *wkvh, *wkvl, *kv2h, *kv2l;
    __nv_bfloat16 *qh, *ql, *kh, *kl, *vv;
    cudaGetSymbolAddress((void**)&xh, g_xh);
    cudaGetSymbolAddress((void**)&xl, g_xl);
    cudaGetSymbolAddress((void**)&wqh, g_wqh);
    cudaGetSymbolAddress((void**)&wql, g_wql);
    cudaGetSymbolAddress((void**)&wkvh, g_wkvh);
    cudaGetSymbolAddress((void**)&wkvl, g_wkvl);
    cudaGetSymbolAddress((void**)&kv2h, g_kv2h);
    cudaGetSymbolAddress((void**)&kv2l, g_kv2l);
    cudaGetSymbolAddress((void**)&qh, g_qh);
    cudaGetSymbolAddress((void**)&ql, g_ql);
    cudaGetSymbolAddress((void**)&kh, g_kh);
    cudaGetSymbolAddress((void**)&kl, g_kl);
    cudaGetSymbolAddress((void**)&vv, g_v);

    const int smem128 = 2 * (2 * 128 * GSTR + 2 * 128 * GSTR) * 2;  // 81920
    const int smem64  = 2 * (2 * 64 * GSTR + 2 * 128 * GSTR) * 2;   // 61440
    cudaFuncSetAttribute((const void*)gemm_mma_kernel<128, 0>,
                         cudaFuncAttributeMaxDynamicSharedMemorySize, smem128);
    cudaFuncSetAttribute((const void*)gemm_mma_kernel<64, 1>,
                         cudaFuncAttributeMaxDynamicSharedMemorySize, smem64);
    cudaFuncSetAttribute((const void*)attn_kernel,
                         cudaFuncAttributeMaxDynamicSharedMemorySize, ATTN_SMEM);

    const float QSC = ATTN_SCALE * 1.4426950408889634f;

    int nx4 = BATCH * NPIX * C / 4;
    split_kernel<<<(nx4 + 255) / 256, 256>>>(x, xh, xl, nx4);
    prep_weights_kernel<<<192 + 49, 256>>>(Wq, Wkv, sr_w1, lw);

    gemm_mma_kernel<128, 0><<<dim3(BATCH * NPIX / 128, C / 128), 256, smem128>>>(
        xh, xl, wqh, wql, bq, qh, ql, nullptr, QSC);
    srconv_kernel<<<dim3(MRED, BATCH), 256>>>(x, bn1g, bn1b, bn1m, bn1v,
                                              sr_w2, bn2g, bn2b, bn2m, bn2v);
    localconv_kernel<<<dim3(MRED, BATCH), 128>>>(lb);
    gemm_mma_kernel<64, 1><<<dim3(BATCH * MRED / 64, 2 * C / 128), 256, smem64>>>(
        kv2h, kv2l, wkvh, wkvl, bkv, kh, kl, vv, 1.0f);
    attn_kernel<<<dim3(NPIX / 256, HEADS, BATCH), 256, ATTN_SMEM>>>(out);
}

// round 13
// speedup vs baseline: 1.1701x; 1.0102x over previous
#include <cuda_runtime.h>
#include <cuda_bf16.h>
#include <math.h>
#include <string.h>

#define BATCH 8
#define C 256
#define NPIX 4096
#define HIMG 64
#define WIMG 64
#define MRED 256
#define HEADS 8
#define HD 32
#define ATTN_SCALE 0.17677669529663687f
#define EPS 1e-5f

// ---------------- scratch ----------------------------------------------------
__device__ float g_kvred[BATCH * MRED * C];   // (b, m, c)
__device__ __nv_bfloat16 g_xh[BATCH * NPIX * C], g_xl[BATCH * NPIX * C];
__device__ __nv_bfloat16 g_wqh[C * C], g_wql[C * C];
__device__ __nv_bfloat16 g_wkvh[2 * C * C], g_wkvl[2 * C * C];
__device__ __nv_bfloat16 g_kv2h[BATCH * MRED * C], g_kv2l[BATCH * MRED * C];
__device__ __nv_bfloat16 g_qh[BATCH * NPIX * C], g_ql[BATCH * NPIX * C];
__device__ __nv_bfloat16 g_kh[BATCH * MRED * C], g_kl[BATCH * MRED * C];
__device__ __nv_bfloat16 g_v[BATCH * MRED * C];
__device__ float g_w7t[49 * C];
__device__ float g_lwt[9 * C];

// ---------------- helpers ------------------------------------------------------
__device__ __forceinline__ unsigned smem_u32(const void* p) {
    unsigned a;
    asm("{ .reg .u64 t; cvta.to.shared.u64 t, %1; cvt.u32.u64 %0, t; }"
        : "=r"(a) : "l"(p));
    return a;
}
__device__ __forceinline__ void cp16(unsigned dst, const void* src) {
    asm volatile("cp.async.ca.shared.global [%0], [%1], 16;"
                 :: "r"(dst), "l"(src));
}
#define CP_COMMIT() asm volatile("cp.async.commit_group;" ::: "memory")
#define CP_WAIT(n)  asm volatile("cp.async.wait_group %0;" :: "n"(n) : "memory")

__device__ __forceinline__ void ldmx4(unsigned* r, unsigned addr) {
    asm volatile("ldmatrix.sync.aligned.m8n8.x4.shared.b16 {%0,%1,%2,%3}, [%4];"
                 : "=r"(r[0]), "=r"(r[1]), "=r"(r[2]), "=r"(r[3]) : "r"(addr));
}
__device__ __forceinline__ void mma_bf16(float* c, const unsigned* a,
                                         unsigned b0, unsigned b1) {
    asm volatile(
        "mma.sync.aligned.m16n8k16.row.col.f32.bf16.bf16.f32 "
        "{%0,%1,%2,%3}, {%4,%5,%6,%7}, {%8,%9}, {%0,%1,%2,%3};"
        : "+f"(c[0]), "+f"(c[1]), "+f"(c[2]), "+f"(c[3])
        : "r"(a[0]), "r"(a[1]), "r"(a[2]), "r"(a[3]), "r"(b0), "r"(b1));
}
__device__ __forceinline__ unsigned pack_bf16x2(float lo, float hi) {
    unsigned d;
    asm("cvt.rn.bf16x2.f32 %0, %1, %2;" : "=r"(d) : "f"(hi), "f"(lo));
    return d;
}
__device__ __forceinline__ void split_store(__nv_bfloat16* hi, __nv_bfloat16* lo,
                                            size_t idx, float a0, float a1) {
    __nv_bfloat16 h0 = __float2bfloat16(a0);
    __nv_bfloat16 h1 = __float2bfloat16(a1);
    *(__nv_bfloat162*)(hi + idx) = __nv_bfloat162(h0, h1);
    *(__nv_bfloat162*)(lo + idx) = __nv_bfloat162(
        __float2bfloat16(a0 - __bfloat162float(h0)),
        __float2bfloat16(a1 - __bfloat162float(h1)));
}
__device__ __forceinline__ unsigned split_pair(float a0, float a1, unsigned& lo) {
    __nv_bfloat16 h0 = __float2bfloat16(a0);
    __nv_bfloat16 h1 = __float2bfloat16(a1);
    __nv_bfloat162 L(__float2bfloat16(a0 - __bfloat162float(h0)),
                     __float2bfloat16(a1 - __bfloat162float(h1)));
    memcpy(&lo, &L, 4);
    __nv_bfloat162 H(h0, h1);
    unsigned h;
    memcpy(&h, &H, 4);
    return h;
}

// ---------------- fp32 -> bf16 hi/lo split (x), 8 elems/thread ---------------
__global__ __launch_bounds__(256) void split_kernel(
    const float* __restrict__ src, __nv_bfloat16* __restrict__ hi,
    __nv_bfloat16* __restrict__ lo, int n8) {
    int i = blockIdx.x * 256 + threadIdx.x;
    if (i >= n8) return;
    float4 a = ((const float4*)src)[2 * i];
    float4 b = ((const float4*)src)[2 * i + 1];
    uint4 H, L;
    H.x = split_pair(a.x, a.y, L.x);
    H.y = split_pair(a.z, a.w, L.y);
    H.z = split_pair(b.x, b.y, L.z);
    H.w = split_pair(b.z, b.w, L.w);
    ((uint4*)hi)[i] = H;
    ((uint4*)lo)[i] = L;
}

// ---------------- weights prep: Wq/Wkv split + conv-weight transpose ----------
__global__ __launch_bounds__(256) void prep_weights_kernel(
    const float* __restrict__ Wq, const float* __restrict__ Wkv,
    const float* __restrict__ w7, const float* __restrict__ lw) {
    int bx = blockIdx.x, tid = threadIdx.x;
    if (bx < 64) {
        int i = bx * 256 + tid;
        float4 v = ((const float4*)Wq)[i];
        split_store(g_wqh, g_wql, 4 * (size_t)i, v.x, v.y);
        split_store(g_wqh, g_wql, 4 * (size_t)i + 2, v.z, v.w);
    } else if (bx < 192) {
        int i = (bx - 64) * 256 + tid;
        float4 v = ((const float4*)Wkv)[i];
        split_store(g_wkvh, g_wkvl, 4 * (size_t)i, v.x, v.y);
        split_store(g_wkvh, g_wkvl, 4 * (size_t)i + 2, v.z, v.w);
    } else {
        int k = bx - 192;
        g_w7t[k * C + tid] = w7[tid * 49 + k];
        if (k < 9) g_lwt[k * C + tid] = lw[tid * 9 + k];
    }
}

// ---------------- HMMA GEMM, bf16-split inputs + cp.async double buffer -------
// Grid: x = bn column (fast), y = bm row -> consecutive blocks share A tile (L2).
#define GSTR 40
template <int BM, int EPI>
__global__ __launch_bounds__(256, 2) void gemm_mma_kernel(
    const __nv_bfloat16* __restrict__ Xh, const __nv_bfloat16* __restrict__ Xl,
    const __nv_bfloat16* __restrict__ Wh, const __nv_bfloat16* __restrict__ Wl,
    const float* __restrict__ bias,
    __nv_bfloat16* __restrict__ Oh, __nv_bfloat16* __restrict__ Ol,
    __nv_bfloat16* __restrict__ Ov, float scale) {
    constexpr int MT = BM / 64;
    constexpr int SX = BM * GSTR;
    constexpr int SW = 128 * GSTR;
    constexpr int STG = 2 * SX + 2 * SW;
    extern __shared__ __nv_bfloat16 gsm[];

    int tid = threadIdx.x, lane = tid & 31, w = tid >> 5;
    int bm = blockIdx.y * BM, bn = blockIdx.x * 128;
    int wm = (w & 3) * (16 * MT), wn = (w >> 2) * 64;
    int lr = tid >> 2, lch = (tid & 3) * 8;

    float acc[MT][8][4];
    #pragma unroll
    for (int mt = 0; mt < MT; mt++)
        #pragma unroll
        for (int nt = 0; nt < 8; nt++)
            #pragma unroll
            for (int q = 0; q < 4; q++) acc[mt][nt][q] = 0.f;

    #define XH(s) (gsm + (s) * STG)
    #define XL(s) (gsm + (s) * STG + SX)
    #define WH(s) (gsm + (s) * STG + 2 * SX)
    #define WL(s) (gsm + (s) * STG + 2 * SX + SW)

    #define LOAD_STAGE(s, kc) do {                                            \
        _Pragma("unroll")                                                      \
        for (int rr = 0; rr < MT; rr++) {                                      \
            cp16(smem_u32(XH(s) + (lr + 64 * rr) * GSTR + lch),                \
                 Xh + (size_t)(bm + lr + 64 * rr) * C + (kc) + lch);           \
            cp16(smem_u32(XL(s) + (lr + 64 * rr) * GSTR + lch),                \
                 Xl + (size_t)(bm + lr + 64 * rr) * C + (kc) + lch);           \
        }                                                                      \
        _Pragma("unroll")                                                      \
        for (int rr = 0; rr < 2; rr++) {                                       \
            cp16(smem_u32(WH(s) + (lr + 64 * rr) * GSTR + lch),                \
                 Wh + (size_t)(bn + lr + 64 * rr) * C + (kc) + lch);           \
            cp16(smem_u32(WL(s) + (lr + 64 * rr) * GSTR + lch),                \
                 Wl + (size_t)(bn + lr + 64 * rr) * C + (kc) + lch);           \
        }                                                                      \
    } while (0)

    LOAD_STAGE(0, 0);
    CP_COMMIT();

    #pragma unroll
    for (int kk = 0; kk < 8; kk++) {
        int s = kk & 1;
        if (kk < 7) {
            LOAD_STAGE(s ^ 1, (kk + 1) * 32);
            CP_COMMIT();
            CP_WAIT(1);
        } else {
            CP_WAIT(0);
        }
        __syncthreads();

        #pragma unroll
        for (int ks = 0; ks < 2; ks++) {
            int acol = ks * 16 + (lane >> 4) * 8;
            int arow = wm + (lane & 15);
            unsigned ah[MT][4], al[MT][4];
            #pragma unroll
            for (int mt = 0; mt < MT; mt++) {
                ldmx4(ah[mt], smem_u32(XH(s) + (arow + mt * 16) * GSTR + acol));
                ldmx4(al[mt], smem_u32(XL(s) + (arow + mt * 16) * GSTR + acol));
            }
            unsigned bh[8][2], bl[8][2];
            #pragma unroll
            for (int nt4 = 0; nt4 < 4; nt4++) {
                int brow = wn + nt4 * 16 + (lane & 15);
                unsigned t[4];
                ldmx4(t, smem_u32(WH(s) + brow * GSTR + acol));
                bh[nt4 * 2][0] = t[0]; bh[nt4 * 2][1] = t[2];
                bh[nt4 * 2 + 1][0] = t[1]; bh[nt4 * 2 + 1][1] = t[3];
                ldmx4(t, smem_u32(WL(s) + brow * GSTR + acol));
                bl[nt4 * 2][0] = t[0]; bl[nt4 * 2][1] = t[2];
                bl[nt4 * 2 + 1][0] = t[1]; bl[nt4 * 2 + 1][1] = t[3];
            }
            #pragma unroll
            for (int mt = 0; mt < MT; mt++)
                #pragma unroll
                for (int nt = 0; nt < 8; nt++) {
                    mma_bf16(acc[mt][nt], ah[mt], bh[nt][0], bh[nt][1]);
                    mma_bf16(acc[mt][nt], ah[mt], bl[nt][0], bl[nt][1]);
                    mma_bf16(acc[mt][nt], al[mt], bh[nt][0], bh[nt][1]);
                }
        }
        __syncthreads();
    }

    int r_in = (lane >> 2), c_in = (lane & 3) * 2;
    #pragma unroll
    for (int mt = 0; mt < MT; mt++)
        #pragma unroll
        for (int nt = 0; nt < 8; nt++) {
            int col = bn + wn + nt * 8 + c_in;
            float b0 = bias[col], b1 = bias[col + 1];
            int row0 = bm + wm + mt * 16 + r_in;
            float s00 = (acc[mt][nt][0] + b0) * scale;
            float s01 = (acc[mt][nt][1] + b1) * scale;
            float s10 = (acc[mt][nt][2] + b0) * scale;
            float s11 = (acc[mt][nt][3] + b1) * scale;
            if (EPI == 0 || col < C) {
                size_t i0 = (size_t)row0 * C + col;
                split_store(Oh, Ol, i0, s00, s01);
                split_store(Oh, Ol, i0 + 8 * C, s10, s11);
            } else {
                size_t i0 = (size_t)row0 * C + (col - C);
                *(__nv_bfloat162*)(Ov + i0) =
                    __nv_bfloat162(__float2bfloat16(s00), __float2bfloat16(s01));
                *(__nv_bfloat162*)(Ov + i0 + 8 * C) =
                    __nv_bfloat162(__float2bfloat16(s10), __float2bfloat16(s11));
            }
        }
    #undef LOAD_STAGE
    #undef XH
    #undef XL
    #undef WH
    #undef WL
}

// ---------------- SR conv (transposed weights, interior fast-path) ------------
__global__ __launch_bounds__(256) void srconv_kernel(
    const float* __restrict__ x,
    const float* __restrict__ g1, const float* __restrict__ b1,
    const float* __restrict__ m1, const float* __restrict__ v1,
    const float* __restrict__ w2,
    const float* __restrict__ g2, const float* __restrict__ b2,
    const float* __restrict__ m2, const float* __restrict__ v2) {
    int opix = blockIdx.x;
    int b = blockIdx.y;
    int c = threadIdx.x;
    int oy = opix >> 4, ox = opix & 15;
    const float* xb = x + (size_t)b * NPIX * C;
    float s = 0.f;
    if (oy >= 1 && ox >= 1) {   // interior: high side never clips (15*4+3 = 63)
        const float* base = xb + (size_t)((oy * 4 - 3) * WIMG + ox * 4 - 3) * C + c;
        #pragma unroll
        for (int ky = 0; ky < 7; ky++) {
            #pragma unroll
            for (int kx = 0; kx < 7; kx++)
                s += base[(size_t)(ky * WIMG + kx) * C] * g_w7t[(ky * 7 + kx) * C + c];
        }
    } else {
        #pragma unroll
        for (int ky = 0; ky < 7; ky++) {
            int iy = oy * 4 - 3 + ky;
            if (iy < 0) continue;
            #pragma unroll
            for (int kx = 0; kx < 7; kx++) {
                int ix = ox * 4 - 3 + kx;
                if (ix < 0) continue;
                s += xb[(size_t)(iy * WIMG + ix) * C + c] * g_w7t[(ky * 7 + kx) * C + c];
            }
        }
    }
    float sc1 = g1[c] * rsqrtf(v1[c] + EPS);
    float val = s * sc1 + (b1[c] - m1[c] * sc1);
    val = 0.5f * val * (1.f + erff(val * 0.7071067811865476f));
    val *= w2[c];
    float sc2 = g2[c] * rsqrtf(v2[c] + EPS);
    val = val * sc2 + (b2[c] - m2[c] * sc2);
    g_kvred[((size_t)b * MRED + opix) * C + c] = val;
}

// ---------------- local 3x3 dwconv + residual -> bf16 hi/lo -------------------
__global__ __launch_bounds__(128) void localconv_kernel(
    const float* __restrict__ lb) {
    int opix = blockIdx.x;
    int b = blockIdx.y;
    int c = threadIdx.x * 2;
    int y = opix >> 4, xq = opix & 15;
    const float* src = g_kvred + (size_t)b * MRED * C;
    float2 ctr = *(const float2*)(src + (size_t)opix * C + c);
    float s0 = lb[c] + ctr.x;
    float s1 = lb[c + 1] + ctr.y;
    #pragma unroll
    for (int dy = -1; dy <= 1; dy++) {
        int yy = y + dy;
        if (yy < 0 || yy >= 16) continue;
        #pragma unroll
        for (int dx = -1; dx <= 1; dx++) {
            int xx = xq + dx;
            if (xx < 0 || xx >= 16) continue;
            float2 wv = *(const float2*)(g_lwt + ((dy + 1) * 3 + (dx + 1)) * C + c);
            float2 sv = *(const float2*)(src + (size_t)(yy * 16 + xx) * C + c);
            s0 += sv.x * wv.x;
            s1 += sv.y * wv.y;
        }
    }
    split_store(g_kv2h, g_kv2l, ((size_t)b * MRED + opix) * C + c, s0, s1);
}

// ---------------- flash attention via mma.sync bf16 ---------------------------
// Block stages K/V once, then processes 4 q-tiles (512 queries) sequentially.
#define QSTR 40
#define VSTR 264
#define SM_KHI 0
#define SM_KLO (SM_KHI + 256 * QSTR)
#define SM_VT  (SM_KLO + 256 * QSTR)
#define ATTN_SMEM ((SM_VT + 32 * VSTR) * 2)

__global__ __launch_bounds__(256, 2) void attn_kernel(float* __restrict__ out) {
    extern __shared__ __nv_bfloat16 sm[];
    __nv_bfloat16* khi = sm + SM_KHI;
    __nv_bfloat16* klo = sm + SM_KLO;
    __nv_bfloat16* vt  = sm + SM_VT;

    int tid = threadIdx.x, lane = tid & 31, w = tid >> 5;
    int head = blockIdx.y, b = blockIdx.z;

    for (int i = tid; i < 1024; i += 256) {
        int m = i >> 2, ch = (i & 3) * 8;
        size_t src = (size_t)(b * MRED + m) * C + head * HD + ch;
        *(uint4*)(khi + m * QSTR + ch) = *(const uint4*)(g_kh + src);
        *(uint4*)(klo + m * QSTR + ch) = *(const uint4*)(g_kl + src);
    }
    for (int i = tid; i < 256 * 16; i += 256) {
        int m = i >> 4, d2 = (i & 15) * 2;
        __nv_bfloat162 v = *(const __nv_bfloat162*)(
            g_v + (size_t)(b * MRED + m) * C + head * HD + d2);
        vt[d2 * VSTR + m] = v.x;
        vt[(d2 + 1) * VSTR + m] = v.y;
    }
    __syncthreads();

    int m0 = w * 16;

    #pragma unroll 1
    for (int qq = 0; qq < 4; qq++) {
        int qtile = blockIdx.x * 4 + qq;

        unsigned qh[2][4], ql[2][4];
        {
            size_t qbase = (size_t)(b * NPIX + qtile * 128 + m0 + (lane >> 2)) * C
                           + head * HD + (lane & 3) * 2;
            #pragma unroll
            for (int kt = 0; kt < 2; kt++) {
                size_t o0 = qbase + kt * 16;
                qh[kt][0] = *(const unsigned*)(g_qh + o0);
                qh[kt][1] = *(const unsigned*)(g_qh + o0 + 8 * C);
                qh[kt][2] = *(const unsigned*)(g_qh + o0 + 8);
                qh[kt][3] = *(const unsigned*)(g_qh + o0 + 8 * C + 8);
                ql[kt][0] = *(const unsigned*)(g_ql + o0);
                ql[kt][1] = *(const unsigned*)(g_ql + o0 + 8 * C);
                ql[kt][2] = *(const unsigned*)(g_ql + o0 + 8);
                ql[kt][3] = *(const unsigned*)(g_ql + o0 + 8 * C + 8);
            }
        }

        float m_lo = -1e30f, m_hi = -1e30f, sum_lo = 0.f, sum_hi = 0.f;
        float o[4][4];
        #pragma unroll
        for (int i = 0; i < 4; i++)
            #pragma unroll
            for (int j = 0; j < 4; j++) o[i][j] = 0.f;

        #pragma unroll
        for (int kb = 0; kb < 4; kb++) {
            float s[8][4];
            #pragma unroll
            for (int j = 0; j < 8; j++)
                #pragma unroll
                for (int q = 0; q < 4; q++) s[j][q] = 0.f;
            #pragma unroll
            for (int kt = 0; kt < 2; kt++) {
                int col = kt * 16 + (lane >> 4) * 8;
                #pragma unroll
                for (int jj = 0; jj < 4; jj++) {
                    int row = kb * 64 + jj * 16 + (lane & 15);
                    unsigned th[4], tl[4];
                    ldmx4(th, smem_u32(khi + row * QSTR + col));
                    ldmx4(tl, smem_u32(klo + row * QSTR + col));
                    mma_bf16(s[2 * jj], qh[kt], th[0], th[2]);
                    mma_bf16(s[2 * jj], qh[kt], tl[0], tl[2]);
                    mma_bf16(s[2 * jj], ql[kt], th[0], th[2]);
                    mma_bf16(s[2 * jj + 1], qh[kt], th[1], th[3]);
                    mma_bf16(s[2 * jj + 1], qh[kt], tl[1], tl[3]);
                    mma_bf16(s[2 * jj + 1], ql[kt], th[1], th[3]);
                }
            }
            float bm_lo = -1e30f, bm_hi = -1e30f;
            #pragma unroll
            for (int j = 0; j < 8; j++) {
                bm_lo = fmaxf(bm_lo, fmaxf(s[j][0], s[j][1]));
                bm_hi = fmaxf(bm_hi, fmaxf(s[j][2], s[j][3]));
            }
            bm_lo = fmaxf(bm_lo, __shfl_xor_sync(0xFFFFFFFFu, bm_lo, 1));
            bm_lo = fmaxf(bm_lo, __shfl_xor_sync(0xFFFFFFFFu, bm_lo, 2));
            bm_hi = fmaxf(bm_hi, __shfl_xor_sync(0xFFFFFFFFu, bm_hi, 1));
            bm_hi = fmaxf(bm_hi, __shfl_xor_sync(0xFFFFFFFFu, bm_hi, 2));
            float nm_lo = fmaxf(m_lo, bm_lo);
            float nm_hi = fmaxf(m_hi, bm_hi);
            float corr_lo = exp2f(m_lo - nm_lo);
            float corr_hi = exp2f(m_hi - nm_hi);
            m_lo = nm_lo; m_hi = nm_hi;
            sum_lo *= corr_lo; sum_hi *= corr_hi;
            #pragma unroll
            for (int dn = 0; dn < 4; dn++) {
                o[dn][0] *= corr_lo; o[dn][1] *= corr_lo;
                o[dn][2] *= corr_hi; o[dn][3] *= corr_hi;
            }
            unsigned pl[8], ph[8];
            #pragma unroll
            for (int j = 0; j < 8; j++) {
                float p0 = exp2f(s[j][0] - m_lo);
                float p1 = exp2f(s[j][1] - m_lo);
                float p2 = exp2f(s[j][2] - m_hi);
                float p3 = exp2f(s[j][3] - m_hi);
                sum_lo += p0 + p1;
                sum_hi += p2 + p3;
                pl[j] = pack_bf16x2(p0, p1);
                ph[j] = pack_bf16x2(p2, p3);
            }
            #pragma unroll
            for (int kt = 0; kt < 4; kt++) {
                unsigned a[4] = {pl[2 * kt], ph[2 * kt],
                                 pl[2 * kt + 1], ph[2 * kt + 1]};
                int kcol = kb * 64 + kt * 16 + (lane >> 4) * 8;
                #pragma unroll
                for (int dn2 = 0; dn2 < 2; dn2++) {
                    int drow = dn2 * 16 + (lane & 15);
                    unsigned t[4];
                    ldmx4(t, smem_u32(vt + drow * VSTR + kcol));
                    mma_bf16(o[2 * dn2], a, t[0], t[2]);
                    mma_bf16(o[2 * dn2 + 1], a, t[1], t[3]);
                }
            }
        }

        sum_lo += __shfl_xor_sync(0xFFFFFFFFu, sum_lo, 1);
        sum_lo += __shfl_xor_sync(0xFFFFFFFFu, sum_lo, 2);
        sum_hi += __shfl_xor_sync(0xFFFFFFFFu, sum_hi, 1);
        sum_hi += __shfl_xor_sync(0xFFFFFFFFu, sum_hi, 2);
        float inv_lo = 1.f / sum_lo;
        float inv_hi = 1.f / sum_hi;
        int r = lane >> 2, cc = (lane & 3) * 2;
        int q0 = qtile * 128 + m0 + r;
        #pragma unroll
        for (int dn = 0; dn < 4; dn++) {
            int d = dn * 8 + cc;
            float2 t0 = make_float2(o[dn][0] * inv_lo, o[dn][1] * inv_lo);
            float2 t1 = make_float2(o[dn][2] * inv_hi, o[dn][3] * inv_hi);
            *(float2*)(out + ((size_t)(b * NPIX + q0)) * C + head * HD + d) = t0;
            *(float2*)(out + ((size_t)(b * NPIX + q0 + 8)) * C + head * HD + d) = t1;
        }
    }
}

// ---------------- launch ------------------------------------------------------
extern "C" void kernel_launch(void* const* d_in, const int* in_sizes, int n_in,
                              void* d_out, int out_size) {
    int base = (n_in >= 19) ? 3 : 1;
    const float* x      = (const float*)d_in[0];
    const float* Wq     = (const float*)d_in[base + 0];
    const float* bq     = (const float*)d_in[base + 1];
    const float* Wkv    = (const float*)d_in[base + 2];
    const float* bkv    = (const float*)d_in[base + 3];
    const float* sr_w1  = (const float*)d_in[base + 4];
    const float* bn1g   = (const float*)d_in[base + 5];
    const float* bn1b   = (const float*)d_in[base + 6];
    const float* bn1m   = (const float*)d_in[base + 7];
    const float* bn1v   = (const float*)d_in[base + 8];
    const float* sr_w2  = (const float*)d_in[base + 9];
    const float* bn2g   = (const float*)d_in[base + 10];
    const float* bn2b   = (const float*)d_in[base + 11];
    const float* bn2m   = (const float*)d_in[base + 12];
    const float* bn2v   = (const float*)d_in[base + 13];
    const float* lw     = (const float*)d_in[base + 14];
    const float* lb     = (const float*)d_in[base + 15];
    float* out = (float*)d_out;

    __nv_bfloat16 *xh, *xl, *wqh, *wql, *wkvh, *wkvl, *kv2h, *kv2l;
    __nv_bfloat16 *qh, *ql, *kh, *kl, *vv;
    cudaGetSymbolAddress((void**)&xh, g_xh);
    cudaGetSymbolAddress((void**)&xl, g_xl);
    cudaGetSymbolAddress((void**)&wqh, g_wqh);
    cudaGetSymbolAddress((void**)&wql, g_wql);
    cudaGetSymbolAddress((void**)&wkvh, g_wkvh);
    cudaGetSymbolAddress((void**)&wkvl, g_wkvl);
    cudaGetSymbolAddress((void**)&kv2h, g_kv2h);
    cudaGetSymbolAddress((void**)&kv2l, g_kv2l);
    cudaGetSymbolAddress((void**)&qh, g_qh);
    cudaGetSymbolAddress((void**)&ql, g_ql);
    cudaGetSymbolAddress((void**)&kh, g_kh);
    cudaGetSymbolAddress((void**)&kl, g_kl);
    cudaGetSymbolAddress((void**)&vv, g_v);

    const int smem128 = 2 * (2 * 128 * GSTR + 2 * 128 * GSTR) * 2;  // 81920
    const int smem64  = 2 * (2 * 64 * GSTR + 2 * 128 * GSTR) * 2;   // 61440
    cudaFuncSetAttribute((const void*)gemm_mma_kernel<128, 0>,
                         cudaFuncAttributeMaxDynamicSharedMemorySize, smem128);
    cudaFuncSetAttribute((const void*)gemm_mma_kernel<64, 1>,
                         cudaFuncAttributeMaxDynamicSharedMemorySize, smem64);
    cudaFuncSetAttribute((const void*)attn_kernel,
                         cudaFuncAttributeMaxDynamicSharedMemorySize, ATTN_SMEM);

    const float QSC = ATTN_SCALE * 1.4426950408889634f;

    int nx8 = BATCH * NPIX * C / 8;
    split_kernel<<<(nx8 + 255) / 256, 256>>>(x, xh, xl, nx8);
    prep_weights_kernel<<<192 + 49, 256>>>(Wq, Wkv, sr_w1, lw);

    // grid.x = bn (fast) so consecutive blocks share the A tile via L2
    gemm_mma_kernel<128, 0><<<dim3(C / 128, BATCH * NPIX / 128), 256, smem128>>>(
        xh, xl, wqh, wql, bq, qh, ql, nullptr, QSC);
    srconv_kernel<<<dim3(MRED, BATCH), 256>>>(x, bn1g, bn1b, bn1m, bn1v,
                                              sr_w2, bn2g, bn2b, bn2m, bn2v);
    localconv_kernel<<<dim3(MRED, BATCH), 128>>>(lb);
    gemm_mma_kernel<64, 1><<<dim3(2 * C / 128, BATCH * MRED / 64), 256, smem64>>>(
        kv2h, kv2l, wkvh, wkvl, bkv, kh, kl, vv, 1.0f);
    attn_kernel<<<dim3(NPIX / 512, HEADS, BATCH), 256, ATTN_SMEM>>>(out);
}

// round 14
// speedup vs baseline: 1.1952x; 1.0214x over previous
#include <cuda_runtime.h>
#include <cuda_bf16.h>
#include <math.h>
#include <string.h>

#define BATCH 8
#define C 256
#define NPIX 4096
#define HIMG 64
#define WIMG 64
#define MRED 256
#define HEADS 8
#define HD 32
#define ATTN_SCALE 0.17677669529663687f
#define EPS 1e-5f

// ---------------- scratch ----------------------------------------------------
__device__ float g_kvred[BATCH * MRED * C];   // (b, m, c)
__device__ __nv_bfloat16 g_xh[BATCH * NPIX * C], g_xl[BATCH * NPIX * C];
__device__ __nv_bfloat16 g_wqh[C * C], g_wql[C * C];
__device__ __nv_bfloat16 g_wkvh[2 * C * C], g_wkvl[2 * C * C];
__device__ __nv_bfloat16 g_kv2h[BATCH * MRED * C], g_kv2l[BATCH * MRED * C];
__device__ __nv_bfloat16 g_qh[BATCH * NPIX * C], g_ql[BATCH * NPIX * C];
__device__ __nv_bfloat16 g_kh[BATCH * MRED * C], g_kl[BATCH * MRED * C];
__device__ __nv_bfloat16 g_v[BATCH * MRED * C];
__device__ float g_w7t[49 * C];
__device__ float g_lwt[9 * C];

// ---------------- helpers ------------------------------------------------------
__device__ __forceinline__ unsigned smem_u32(const void* p) {
    unsigned a;
    asm("{ .reg .u64 t; cvta.to.shared.u64 t, %1; cvt.u32.u64 %0, t; }"
        : "=r"(a) : "l"(p));
    return a;
}
__device__ __forceinline__ void cp16(unsigned dst, const void* src) {
    asm volatile("cp.async.ca.shared.global [%0], [%1], 16;"
                 :: "r"(dst), "l"(src));
}
#define CP_COMMIT() asm volatile("cp.async.commit_group;" ::: "memory")
#define CP_WAIT(n)  asm volatile("cp.async.wait_group %0;" :: "n"(n) : "memory")

__device__ __forceinline__ void ldmx4(unsigned* r, unsigned addr) {
    asm volatile("ldmatrix.sync.aligned.m8n8.x4.shared.b16 {%0,%1,%2,%3}, [%4];"
                 : "=r"(r[0]), "=r"(r[1]), "=r"(r[2]), "=r"(r[3]) : "r"(addr));
}
__device__ __forceinline__ void mma_bf16(float* c, const unsigned* a,
                                         unsigned b0, unsigned b1) {
    asm volatile(
        "mma.sync.aligned.m16n8k16.row.col.f32.bf16.bf16.f32 "
        "{%0,%1,%2,%3}, {%4,%5,%6,%7}, {%8,%9}, {%0,%1,%2,%3};"
        : "+f"(c[0]), "+f"(c[1]), "+f"(c[2]), "+f"(c[3])
        : "r"(a[0]), "r"(a[1]), "r"(a[2]), "r"(a[3]), "r"(b0), "r"(b1));
}
__device__ __forceinline__ unsigned pack_bf16x2(float lo, float hi) {
    unsigned d;
    asm("cvt.rn.bf16x2.f32 %0, %1, %2;" : "=r"(d) : "f"(hi), "f"(lo));
    return d;
}
__device__ __forceinline__ void split_store(__nv_bfloat16* hi, __nv_bfloat16* lo,
                                            size_t idx, float a0, float a1) {
    __nv_bfloat16 h0 = __float2bfloat16(a0);
    __nv_bfloat16 h1 = __float2bfloat16(a1);
    *(__nv_bfloat162*)(hi + idx) = __nv_bfloat162(h0, h1);
    *(__nv_bfloat162*)(lo + idx) = __nv_bfloat162(
        __float2bfloat16(a0 - __bfloat162float(h0)),
        __float2bfloat16(a1 - __bfloat162float(h1)));
}

// ---------------- weights prep: Wq/Wkv split + conv-weight transpose ----------
__global__ __launch_bounds__(256) void prep_weights_kernel(
    const float* __restrict__ Wq, const float* __restrict__ Wkv,
    const float* __restrict__ w7, const float* __restrict__ lw) {
    int bx = blockIdx.x, tid = threadIdx.x;
    if (bx < 64) {
        int i = bx * 256 + tid;
        float4 v = ((const float4*)Wq)[i];
        split_store(g_wqh, g_wql, 4 * (size_t)i, v.x, v.y);
        split_store(g_wqh, g_wql, 4 * (size_t)i + 2, v.z, v.w);
    } else if (bx < 192) {
        int i = (bx - 64) * 256 + tid;
        float4 v = ((const float4*)Wkv)[i];
        split_store(g_wkvh, g_wkvl, 4 * (size_t)i, v.x, v.y);
        split_store(g_wkvh, g_wkvl, 4 * (size_t)i + 2, v.z, v.w);
    } else {
        int k = bx - 192;
        g_w7t[k * C + tid] = w7[tid * 49 + k];
        if (k < 9) g_lwt[k * C + tid] = lw[tid * 9 + k];
    }
}

// ---------------- HMMA GEMM, bf16-split inputs + cp.async double buffer -------
#define GSTR 40
template <int BM, int EPI>
__global__ __launch_bounds__(256, 2) void gemm_mma_kernel(
    const __nv_bfloat16* __restrict__ Xh, const __nv_bfloat16* __restrict__ Xl,
    const __nv_bfloat16* __restrict__ Wh, const __nv_bfloat16* __restrict__ Wl,
    const float* __restrict__ bias,
    __nv_bfloat16* __restrict__ Oh, __nv_bfloat16* __restrict__ Ol,
    __nv_bfloat16* __restrict__ Ov, float scale) {
    constexpr int MT = BM / 64;
    constexpr int SX = BM * GSTR;
    constexpr int SW = 128 * GSTR;
    constexpr int STG = 2 * SX + 2 * SW;
    extern __shared__ __nv_bfloat16 gsm[];

    int tid = threadIdx.x, lane = tid & 31, w = tid >> 5;
    int bm = blockIdx.y * BM, bn = blockIdx.x * 128;
    int wm = (w & 3) * (16 * MT), wn = (w >> 2) * 64;
    int lr = tid >> 2, lch = (tid & 3) * 8;

    float acc[MT][8][4];
    #pragma unroll
    for (int mt = 0; mt < MT; mt++)
        #pragma unroll
        for (int nt = 0; nt < 8; nt++)
            #pragma unroll
            for (int q = 0; q < 4; q++) acc[mt][nt][q] = 0.f;

    #define XH(s) (gsm + (s) * STG)
    #define XL(s) (gsm + (s) * STG + SX)
    #define WH(s) (gsm + (s) * STG + 2 * SX)
    #define WL(s) (gsm + (s) * STG + 2 * SX + SW)

    #define LOAD_STAGE(s, kc) do {                                            \
        _Pragma("unroll")                                                      \
        for (int rr = 0; rr < MT; rr++) {                                      \
            cp16(smem_u32(XH(s) + (lr + 64 * rr) * GSTR + lch),                \
                 Xh + (size_t)(bm + lr + 64 * rr) * C + (kc) + lch);           \
            cp16(smem_u32(XL(s) + (lr + 64 * rr) * GSTR + lch),                \
                 Xl + (size_t)(bm + lr + 64 * rr) * C + (kc) + lch);           \
        }                                                                      \
        _Pragma("unroll")                                                      \
        for (int rr = 0; rr < 2; rr++) {                                       \
            cp16(smem_u32(WH(s) + (lr + 64 * rr) * GSTR + lch),                \
                 Wh + (size_t)(bn + lr + 64 * rr) * C + (kc) + lch);           \
            cp16(smem_u32(WL(s) + (lr + 64 * rr) * GSTR + lch),                \
                 Wl + (size_t)(bn + lr + 64 * rr) * C + (kc) + lch);           \
        }                                                                      \
    } while (0)

    LOAD_STAGE(0, 0);
    CP_COMMIT();

    #pragma unroll
    for (int kk = 0; kk < 8; kk++) {
        int s = kk & 1;
        if (kk < 7) {
            LOAD_STAGE(s ^ 1, (kk + 1) * 32);
            CP_COMMIT();
            CP_WAIT(1);
        } else {
            CP_WAIT(0);
        }
        __syncthreads();

        #pragma unroll
        for (int ks = 0; ks < 2; ks++) {
            int acol = ks * 16 + (lane >> 4) * 8;
            int arow = wm + (lane & 15);
            unsigned ah[MT][4], al[MT][4];
            #pragma unroll
            for (int mt = 0; mt < MT; mt++) {
                ldmx4(ah[mt], smem_u32(XH(s) + (arow + mt * 16) * GSTR + acol));
                ldmx4(al[mt], smem_u32(XL(s) + (arow + mt * 16) * GSTR + acol));
            }
            unsigned bh[8][2], bl[8][2];
            #pragma unroll
            for (int nt4 = 0; nt4 < 4; nt4++) {
                int brow = wn + nt4 * 16 + (lane & 15);
                unsigned t[4];
                ldmx4(t, smem_u32(WH(s) + brow * GSTR + acol));
                bh[nt4 * 2][0] = t[0]; bh[nt4 * 2][1] = t[2];
                bh[nt4 * 2 + 1][0] = t[1]; bh[nt4 * 2 + 1][1] = t[3];
                ldmx4(t, smem_u32(WL(s) + brow * GSTR + acol));
                bl[nt4 * 2][0] = t[0]; bl[nt4 * 2][1] = t[2];
                bl[nt4 * 2 + 1][0] = t[1]; bl[nt4 * 2 + 1][1] = t[3];
            }
            #pragma unroll
            for (int mt = 0; mt < MT; mt++)
                #pragma unroll
                for (int nt = 0; nt < 8; nt++) {
                    mma_bf16(acc[mt][nt], ah[mt], bh[nt][0], bh[nt][1]);
                    mma_bf16(acc[mt][nt], ah[mt], bl[nt][0], bl[nt][1]);
                    mma_bf16(acc[mt][nt], al[mt], bh[nt][0], bh[nt][1]);
                }
        }
        __syncthreads();
    }

    int r_in = (lane >> 2), c_in = (lane & 3) * 2;
    #pragma unroll
    for (int mt = 0; mt < MT; mt++)
        #pragma unroll
        for (int nt = 0; nt < 8; nt++) {
            int col = bn + wn + nt * 8 + c_in;
            float b0 = bias[col], b1 = bias[col + 1];
            int row0 = bm + wm + mt * 16 + r_in;
            float s00 = (acc[mt][nt][0] + b0) * scale;
            float s01 = (acc[mt][nt][1] + b1) * scale;
            float s10 = (acc[mt][nt][2] + b0) * scale;
            float s11 = (acc[mt][nt][3] + b1) * scale;
            if (EPI == 0 || col < C) {
                size_t i0 = (size_t)row0 * C + col;
                split_store(Oh, Ol, i0, s00, s01);
                split_store(Oh, Ol, i0 + 8 * C, s10, s11);
            } else {
                size_t i0 = (size_t)row0 * C + (col - C);
                *(__nv_bfloat162*)(Ov + i0) =
                    __nv_bfloat162(__float2bfloat16(s00), __float2bfloat16(s01));
                *(__nv_bfloat162*)(Ov + i0 + 8 * C) =
                    __nv_bfloat162(__float2bfloat16(s10), __float2bfloat16(s11));
            }
        }
    #undef LOAD_STAGE
    #undef XH
    #undef XL
    #undef WH
    #undef WL
}

// ---------------- SR conv + fused x split (re-read, 2 channels/thread) --------
__global__ __launch_bounds__(128) void srconv_kernel(
    const float* __restrict__ x,
    const float* __restrict__ g1, const float* __restrict__ b1,
    const float* __restrict__ m1, const float* __restrict__ v1,
    const float* __restrict__ w2,
    const float* __restrict__ g2, const float* __restrict__ b2,
    const float* __restrict__ m2, const float* __restrict__ v2) {
    int opix = blockIdx.x;
    int b = blockIdx.y;
    int c = threadIdx.x * 2;
    int oy = opix >> 4, ox = opix & 15;
    const float* xb = x + (size_t)b * NPIX * C;
    float s0 = 0.f, s1 = 0.f;

    if (oy >= 1 && ox >= 1) {   // interior: high side never clips (15*4+3 = 63)
        const float* base = xb + (size_t)((oy * 4 - 3) * WIMG + ox * 4 - 3) * C + c;
        #pragma unroll
        for (int ky = 0; ky < 7; ky++) {
            #pragma unroll
            for (int kx = 0; kx < 7; kx++) {
                float2 v = *(const float2*)(base + (size_t)(ky * WIMG + kx) * C);
                float2 wv = *(const float2*)(g_w7t + (ky * 7 + kx) * C + c);
                s0 += v.x * wv.x;
                s1 += v.y * wv.y;
            }
        }
    } else {
        #pragma unroll
        for (int ky = 0; ky < 7; ky++) {
            int iy = oy * 4 - 3 + ky;
            if (iy < 0) continue;
            #pragma unroll
            for (int kx = 0; kx < 7; kx++) {
                int ix = ox * 4 - 3 + kx;
                if (ix < 0) continue;
                float2 v = *(const float2*)(xb + (size_t)(iy * WIMG + ix) * C + c);
                float2 wv = *(const float2*)(g_w7t + (ky * 7 + kx) * C + c);
                s0 += v.x * wv.x;
                s1 += v.y * wv.y;
            }
        }
    }

    // fused x hi/lo split: re-read the 16 owned pixels (L2-hot), split-store
    {
        size_t pbase = (size_t)b * NPIX * C;
        #pragma unroll
        for (int p = 0; p < 16; p++) {
            int ip = (oy * 4 + (p >> 2)) * WIMG + ox * 4 + (p & 3);
            size_t idx = (size_t)ip * C + c;
            float2 v = *(const float2*)(xb + idx);
            split_store(g_xh, g_xl, pbase + idx, v.x, v.y);
        }
    }

    // BN1 + GELU + w2 + BN2 for 2 channels
    float sc1a = g1[c] * rsqrtf(v1[c] + EPS);
    float sc1b = g1[c + 1] * rsqrtf(v1[c + 1] + EPS);
    float va = s0 * sc1a + (b1[c] - m1[c] * sc1a);
    float vb = s1 * sc1b + (b1[c + 1] - m1[c + 1] * sc1b);
    va = 0.5f * va * (1.f + erff(va * 0.7071067811865476f));
    vb = 0.5f * vb * (1.f + erff(vb * 0.7071067811865476f));
    va *= w2[c];
    vb *= w2[c + 1];
    float sc2a = g2[c] * rsqrtf(v2[c] + EPS);
    float sc2b = g2[c + 1] * rsqrtf(v2[c + 1] + EPS);
    va = va * sc2a + (b2[c] - m2[c] * sc2a);
    vb = vb * sc2b + (b2[c + 1] - m2[c + 1] * sc2b);
    *(float2*)(g_kvred + ((size_t)b * MRED + opix) * C + c) = make_float2(va, vb);
}

// ---------------- local 3x3 dwconv + residual -> bf16 hi/lo -------------------
__global__ __launch_bounds__(128) void localconv_kernel(
    const float* __restrict__ lb) {
    int opix = blockIdx.x;
    int b = blockIdx.y;
    int c = threadIdx.x * 2;
    int y = opix >> 4, xq = opix & 15;
    const float* src = g_kvred + (size_t)b * MRED * C;
    float2 ctr = *(const float2*)(src + (size_t)opix * C + c);
    float s0 = lb[c] + ctr.x;
    float s1 = lb[c + 1] + ctr.y;
    #pragma unroll
    for (int dy = -1; dy <= 1; dy++) {
        int yy = y + dy;
        if (yy < 0 || yy >= 16) continue;
        #pragma unroll
        for (int dx = -1; dx <= 1; dx++) {
            int xx = xq + dx;
            if (xx < 0 || xx >= 16) continue;
            float2 wv = *(const float2*)(g_lwt + ((dy + 1) * 3 + (dx + 1)) * C + c);
            float2 sv = *(const float2*)(src + (size_t)(yy * 16 + xx) * C + c);
            s0 += sv.x * wv.x;
            s1 += sv.y * wv.y;
        }
    }
    split_store(g_kv2h, g_kv2l, ((size_t)b * MRED + opix) * C + c, s0, s1);
}

// ---------------- flash attention via mma.sync bf16 ---------------------------
#define QSTR 40
#define VSTR 264
#define SM_KHI 0
#define SM_KLO (SM_KHI + 256 * QSTR)
#define SM_VT  (SM_KLO + 256 * QSTR)
#define ATTN_SMEM ((SM_VT + 32 * VSTR) * 2)

__global__ __launch_bounds__(256, 2) void attn_kernel(float* __restrict__ out) {
    extern __shared__ __nv_bfloat16 sm[];
    __nv_bfloat16* khi = sm + SM_KHI;
    __nv_bfloat16* klo = sm + SM_KLO;
    __nv_bfloat16* vt  = sm + SM_VT;

    int tid = threadIdx.x, lane = tid & 31, w = tid >> 5;
    int head = blockIdx.y, b = blockIdx.z;

    for (int i = tid; i < 1024; i += 256) {
        int m = i >> 2, ch = (i & 3) * 8;
        size_t src = (size_t)(b * MRED + m) * C + head * HD + ch;
        *(uint4*)(khi + m * QSTR + ch) = *(const uint4*)(g_kh + src);
        *(uint4*)(klo + m * QSTR + ch) = *(const uint4*)(g_kl + src);
    }
    for (int i = tid; i < 256 * 16; i += 256) {
        int m = i >> 4, d2 = (i & 15) * 2;
        __nv_bfloat162 v = *(const __nv_bfloat162*)(
            g_v + (size_t)(b * MRED + m) * C + head * HD + d2);
        vt[d2 * VSTR + m] = v.x;
        vt[(d2 + 1) * VSTR + m] = v.y;
    }
    __syncthreads();

    int m0 = w * 16;

    #pragma unroll 1
    for (int qq = 0; qq < 4; qq++) {
        int qtile = blockIdx.x * 4 + qq;

        unsigned qh[2][4], ql[2][4];
        {
            size_t qbase = (size_t)(b * NPIX + qtile * 128 + m0 + (lane >> 2)) * C
                           + head * HD + (lane & 3) * 2;
            #pragma unroll
            for (int kt = 0; kt < 2; kt++) {
                size_t o0 = qbase + kt * 16;
                qh[kt][0] = *(const unsigned*)(g_qh + o0);
                qh[kt][1] = *(const unsigned*)(g_qh + o0 + 8 * C);
                qh[kt][2] = *(const unsigned*)(g_qh + o0 + 8);
                qh[kt][3] = *(const unsigned*)(g_qh + o0 + 8 * C + 8);
                ql[kt][0] = *(const unsigned*)(g_ql + o0);
                ql[kt][1] = *(const unsigned*)(g_ql + o0 + 8 * C);
                ql[kt][2] = *(const unsigned*)(g_ql + o0 + 8);
                ql[kt][3] = *(const unsigned*)(g_ql + o0 + 8 * C + 8);
            }
        }

        float m_lo = -1e30f, m_hi = -1e30f, sum_lo = 0.f, sum_hi = 0.f;
        float o[4][4];
        #pragma unroll
        for (int i = 0; i < 4; i++)
            #pragma unroll
            for (int j = 0; j < 4; j++) o[i][j] = 0.f;

        #pragma unroll
        for (int kb = 0; kb < 4; kb++) {
            float s[8][4];
            #pragma unroll
            for (int j = 0; j < 8; j++)
                #pragma unroll
                for (int q = 0; q < 4; q++) s[j][q] = 0.f;
            #pragma unroll
            for (int kt = 0; kt < 2; kt++) {
                int col = kt * 16 + (lane >> 4) * 8;
                #pragma unroll
                for (int jj = 0; jj < 4; jj++) {
                    int row = kb * 64 + jj * 16 + (lane & 15);
                    unsigned th[4], tl[4];
                    ldmx4(th, smem_u32(khi + row * QSTR + col));
                    ldmx4(tl, smem_u32(klo + row * QSTR + col));
                    mma_bf16(s[2 * jj], qh[kt], th[0], th[2]);
                    mma_bf16(s[2 * jj], qh[kt], tl[0], tl[2]);
                    mma_bf16(s[2 * jj], ql[kt], th[0], th[2]);
                    mma_bf16(s[2 * jj + 1], qh[kt], th[1], th[3]);
                    mma_bf16(s[2 * jj + 1], qh[kt], tl[1], tl[3]);
                    mma_bf16(s[2 * jj + 1], ql[kt], th[1], th[3]);
                }
            }
            float bm_lo = -1e30f, bm_hi = -1e30f;
            #pragma unroll
            for (int j = 0; j < 8; j++) {
                bm_lo = fmaxf(bm_lo, fmaxf(s[j][0], s[j][1]));
                bm_hi = fmaxf(bm_hi, fmaxf(s[j][2], s[j][3]));
            }
            bm_lo = fmaxf(bm_lo, __shfl_xor_sync(0xFFFFFFFFu, bm_lo, 1));
            bm_lo = fmaxf(bm_lo, __shfl_xor_sync(0xFFFFFFFFu, bm_lo, 2));
            bm_hi = fmaxf(bm_hi, __shfl_xor_sync(0xFFFFFFFFu, bm_hi, 1));
            bm_hi = fmaxf(bm_hi, __shfl_xor_sync(0xFFFFFFFFu, bm_hi, 2));
            float nm_lo = fmaxf(m_lo, bm_lo);
            float nm_hi = fmaxf(m_hi, bm_hi);
            float corr_lo = exp2f(m_lo - nm_lo);
            float corr_hi = exp2f(m_hi - nm_hi);
            m_lo = nm_lo; m_hi = nm_hi;
            sum_lo *= corr_lo; sum_hi *= corr_hi;
            #pragma unroll
            for (int dn = 0; dn < 4; dn++) {
                o[dn][0] *= corr_lo; o[dn][1] *= corr_lo;
                o[dn][2] *= corr_hi; o[dn][3] *= corr_hi;
            }
            unsigned pl[8], ph[8];
            #pragma unroll
            for (int j = 0; j < 8; j++) {
                float p0 = exp2f(s[j][0] - m_lo);
                float p1 = exp2f(s[j][1] - m_lo);
                float p2 = exp2f(s[j][2] - m_hi);
                float p3 = exp2f(s[j][3] - m_hi);
                sum_lo += p0 + p1;
                sum_hi += p2 + p3;
                pl[j] = pack_bf16x2(p0, p1);
                ph[j] = pack_bf16x2(p2, p3);
            }
            #pragma unroll
            for (int kt = 0; kt < 4; kt++) {
                unsigned a[4] = {pl[2 * kt], ph[2 * kt],
                                 pl[2 * kt + 1], ph[2 * kt + 1]};
                int kcol = kb * 64 + kt * 16 + (lane >> 4) * 8;
                #pragma unroll
                for (int dn2 = 0; dn2 < 2; dn2++) {
                    int drow = dn2 * 16 + (lane & 15);
                    unsigned t[4];
                    ldmx4(t, smem_u32(vt + drow * VSTR + kcol));
                    mma_bf16(o[2 * dn2], a, t[0], t[2]);
                    mma_bf16(o[2 * dn2 + 1], a, t[1], t[3]);
                }
            }
        }

        sum_lo += __shfl_xor_sync(0xFFFFFFFFu, sum_lo, 1);
        sum_lo += __shfl_xor_sync(0xFFFFFFFFu, sum_lo, 2);
        sum_hi += __shfl_xor_sync(0xFFFFFFFFu, sum_hi, 1);
        sum_hi += __shfl_xor_sync(0xFFFFFFFFu, sum_hi, 2);
        float inv_lo = 1.f / sum_lo;
        float inv_hi = 1.f / sum_hi;
        int r = lane >> 2, cc = (lane & 3) * 2;
        int q0 = qtile * 128 + m0 + r;
        #pragma unroll
        for (int dn = 0; dn < 4; dn++) {
            int d = dn * 8 + cc;
            float2 t0 = make_float2(o[dn][0] * inv_lo, o[dn][1] * inv_lo);
            float2 t1 = make_float2(o[dn][2] * inv_hi, o[dn][3] * inv_hi);
            *(float2*)(out + ((size_t)(b * NPIX + q0)) * C + head * HD + d) = t0;
            *(float2*)(out + ((size_t)(b * NPIX + q0 + 8)) * C + head * HD + d) = t1;
        }
    }
}

// ---------------- launch ------------------------------------------------------
extern "C" void kernel_launch(void* const* d_in, const int* in_sizes, int n_in,
                              void* d_out, int out_size) {
    int base = (n_in >= 19) ? 3 : 1;
    const float* x      = (const float*)d_in[0];
    const float* Wq     = (const float*)d_in[base + 0];
    const float* bq     = (const float*)d_in[base + 1];
    const float* Wkv    = (const float*)d_in[base + 2];
    const float* bkv    = (const float*)d_in[base + 3];
    const float* sr_w1  = (const float*)d_in[base + 4];
    const float* bn1g   = (const float*)d_in[base + 5];
    const float* bn1b   = (const float*)d_in[base + 6];
    const float* bn1m   = (const float*)d_in[base + 7];
    const float* bn1v   = (const float*)d_in[base + 8];
    const float* sr_w2  = (const float*)d_in[base + 9];
    const float* bn2g   = (const float*)d_in[base + 10];
    const float* bn2b   = (const float*)d_in[base + 11];
    const float* bn2m   = (const float*)d_in[base + 12];
    const float* bn2v   = (const float*)d_in[base + 13];
    const float* lw     = (const float*)d_in[base + 14];
    const float* lb     = (const float*)d_in[base + 15];
    float* out = (float*)d_out;

    __nv_bfloat16 *xh, *xl, *wqh, *wql, *wkvh, *wkvl, *kv2h, *kv2l;
    __nv_bfloat16 *qh, *ql, *kh, *kl, *vv;
    cudaGetSymbolAddress((void**)&xh, g_xh);
    cudaGetSymbolAddress((void**)&xl, g_xl);
    cudaGetSymbolAddress((void**)&wqh, g_wqh);
    cudaGetSymbolAddress((void**)&wql, g_wql);
    cudaGetSymbolAddress((void**)&wkvh, g_wkvh);
    cudaGetSymbolAddress((void**)&wkvl, g_wkvl);
    cudaGetSymbolAddress((void**)&kv2h, g_kv2h);
    cudaGetSymbolAddress((void**)&kv2l, g_kv2l);
    cudaGetSymbolAddress((void**)&qh, g_qh);
    cudaGetSymbolAddress((void**)&ql, g_ql);
    cudaGetSymbolAddress((void**)&kh, g_kh);
    cudaGetSymbolAddress((void**)&kl, g_kl);
    cudaGetSymbolAddress((void**)&vv, g_v);

    const int smem128 = 2 * (2 * 128 * GSTR + 2 * 128 * GSTR) * 2;  // 81920
    const int smem64  = 2 * (2 * 64 * GSTR + 2 * 128 * GSTR) * 2;   // 61440
    cudaFuncSetAttribute((const void*)gemm_mma_kernel<128, 0>,
                         cudaFuncAttributeMaxDynamicSharedMemorySize, smem128);
    cudaFuncSetAttribute((const void*)gemm_mma_kernel<64, 1>,
                         cudaFuncAttributeMaxDynamicSharedMemorySize, smem64);
    cudaFuncSetAttribute((const void*)attn_kernel,
                         cudaFuncAttributeMaxDynamicSharedMemorySize, ATTN_SMEM);

    const float QSC = ATTN_SCALE * 1.4426950408889634f;

    prep_weights_kernel<<<192 + 49, 256>>>(Wq, Wkv, sr_w1, lw);
    // srconv also emits g_xh/g_xl (fused split via L2 re-read)
    srconv_kernel<<<dim3(MRED, BATCH), 128>>>(x, bn1g, bn1b, bn1m, bn1v,
                                              sr_w2, bn2g, bn2b, bn2m, bn2v);
    localconv_kernel<<<dim3(MRED, BATCH), 128>>>(lb);
    gemm_mma_kernel<64, 1><<<dim3(2 * C / 128, BATCH * MRED / 64), 256, smem64>>>(
        kv2h, kv2l, wkvh, wkvl, bkv, kh, kl, vv, 1.0f);
    gemm_mma_kernel<128, 0><<<dim3(C / 128, BATCH * NPIX / 128), 256, smem128>>>(
        xh, xl, wqh, wql, bq, qh, ql, nullptr, QSC);
    attn_kernel<<<dim3(NPIX / 512, HEADS, BATCH), 256, ATTN_SMEM>>>(out);
}

// round 15
// speedup vs baseline: 1.4394x; 1.2044x over previous
#include <cuda_runtime.h>
#include <cuda_bf16.h>
#include <cuda_fp16.h>
#include <math.h>
#include <string.h>

#define BATCH 8
#define C 256
#define NPIX 4096
#define HIMG 64
#define WIMG 64
#define MRED 256
#define HEADS 8
#define HD 32
#define ATTN_SCALE 0.17677669529663687f
#define EPS 1e-5f

// ---------------- scratch ----------------------------------------------------
__device__ float g_kvred[BATCH * MRED * C];   // (b, m, c)
__device__ __nv_bfloat16 g_xh[BATCH * NPIX * C], g_xl[BATCH * NPIX * C];
__device__ __nv_bfloat16 g_wqh[C * C], g_wql[C * C];
__device__ __nv_bfloat16 g_wkvh[2 * C * C], g_wkvl[2 * C * C];
__device__ __nv_bfloat16 g_kv2h[BATCH * MRED * C], g_kv2l[BATCH * MRED * C];
// fp16 attention operands
__device__ __half g_qf[BATCH * NPIX * C];     // pre-scaled q
__device__ __half g_kf[BATCH * MRED * C];
__device__ __half g_vf[BATCH * MRED * C];
__device__ float g_w7t[49 * C];
__device__ float g_lwt[9 * C];

// ---------------- helpers ------------------------------------------------------
__device__ __forceinline__ unsigned smem_u32(const void* p) {
    unsigned a;
    asm("{ .reg .u64 t; cvta.to.shared.u64 t, %1; cvt.u32.u64 %0, t; }"
        : "=r"(a) : "l"(p));
    return a;
}
__device__ __forceinline__ void cp16(unsigned dst, const void* src) {
    asm volatile("cp.async.ca.shared.global [%0], [%1], 16;"
                 :: "r"(dst), "l"(src));
}
#define CP_COMMIT() asm volatile("cp.async.commit_group;" ::: "memory")
#define CP_WAIT(n)  asm volatile("cp.async.wait_group %0;" :: "n"(n) : "memory")

__device__ __forceinline__ void ldmx4(unsigned* r, unsigned addr) {
    asm volatile("ldmatrix.sync.aligned.m8n8.x4.shared.b16 {%0,%1,%2,%3}, [%4];"
                 : "=r"(r[0]), "=r"(r[1]), "=r"(r[2]), "=r"(r[3]) : "r"(addr));
}
__device__ __forceinline__ void mma_bf16(float* c, const unsigned* a,
                                         unsigned b0, unsigned b1) {
    asm volatile(
        "mma.sync.aligned.m16n8k16.row.col.f32.bf16.bf16.f32 "
        "{%0,%1,%2,%3}, {%4,%5,%6,%7}, {%8,%9}, {%0,%1,%2,%3};"
        : "+f"(c[0]), "+f"(c[1]), "+f"(c[2]), "+f"(c[3])
        : "r"(a[0]), "r"(a[1]), "r"(a[2]), "r"(a[3]), "r"(b0), "r"(b1));
}
__device__ __forceinline__ void mma_fp16(float* c, const unsigned* a,
                                         unsigned b0, unsigned b1) {
    asm volatile(
        "mma.sync.aligned.m16n8k16.row.col.f32.f16.f16.f32 "
        "{%0,%1,%2,%3}, {%4,%5,%6,%7}, {%8,%9}, {%0,%1,%2,%3};"
        : "+f"(c[0]), "+f"(c[1]), "+f"(c[2]), "+f"(c[3])
        : "r"(a[0]), "r"(a[1]), "r"(a[2]), "r"(a[3]), "r"(b0), "r"(b1));
}
__device__ __forceinline__ unsigned pack_f16x2(float lo, float hi) {
    unsigned d;
    asm("cvt.rn.f16x2.f32 %0, %1, %2;" : "=r"(d) : "f"(hi), "f"(lo));
    return d;
}
__device__ __forceinline__ void split_store(__nv_bfloat16* hi, __nv_bfloat16* lo,
                                            size_t idx, float a0, float a1) {
    __nv_bfloat16 h0 = __float2bfloat16(a0);
    __nv_bfloat16 h1 = __float2bfloat16(a1);
    *(__nv_bfloat162*)(hi + idx) = __nv_bfloat162(h0, h1);
    *(__nv_bfloat162*)(lo + idx) = __nv_bfloat162(
        __float2bfloat16(a0 - __bfloat162float(h0)),
        __float2bfloat16(a1 - __bfloat162float(h1)));
}

// ---------------- weights prep: Wq/Wkv split + conv-weight transpose ----------
__global__ __launch_bounds__(256) void prep_weights_kernel(
    const float* __restrict__ Wq, const float* __restrict__ Wkv,
    const float* __restrict__ w7, const float* __restrict__ lw) {
    int bx = blockIdx.x, tid = threadIdx.x;
    if (bx < 64) {
        int i = bx * 256 + tid;
        float4 v = ((const float4*)Wq)[i];
        split_store(g_wqh, g_wql, 4 * (size_t)i, v.x, v.y);
        split_store(g_wqh, g_wql, 4 * (size_t)i + 2, v.z, v.w);
    } else if (bx < 192) {
        int i = (bx - 64) * 256 + tid;
        float4 v = ((const float4*)Wkv)[i];
        split_store(g_wkvh, g_wkvl, 4 * (size_t)i, v.x, v.y);
        split_store(g_wkvh, g_wkvl, 4 * (size_t)i + 2, v.z, v.w);
    } else {
        int k = bx - 192;
        g_w7t[k * C + tid] = w7[tid * 49 + k];
        if (k < 9) g_lwt[k * C + tid] = lw[tid * 9 + k];
    }
}

// ---------------- HMMA GEMM, bf16-split inputs + cp.async double buffer -------
// EPI 0: q-style (scale, fp16 out). EPI 1: kv-style (fp16 K and V out).
#define GSTR 40
template <int BM, int EPI>
__global__ __launch_bounds__(256, 2) void gemm_mma_kernel(
    const __nv_bfloat16* __restrict__ Xh, const __nv_bfloat16* __restrict__ Xl,
    const __nv_bfloat16* __restrict__ Wh, const __nv_bfloat16* __restrict__ Wl,
    const float* __restrict__ bias,
    __half* __restrict__ O1, __half* __restrict__ O2, float scale) {
    constexpr int MT = BM / 64;
    constexpr int SX = BM * GSTR;
    constexpr int SW = 128 * GSTR;
    constexpr int STG = 2 * SX + 2 * SW;
    extern __shared__ __nv_bfloat16 gsm[];

    int tid = threadIdx.x, lane = tid & 31, w = tid >> 5;
    int bm = blockIdx.y * BM, bn = blockIdx.x * 128;
    int wm = (w & 3) * (16 * MT), wn = (w >> 2) * 64;
    int lr = tid >> 2, lch = (tid & 3) * 8;

    float acc[MT][8][4];
    #pragma unroll
    for (int mt = 0; mt < MT; mt++)
        #pragma unroll
        for (int nt = 0; nt < 8; nt++)
            #pragma unroll
            for (int q = 0; q < 4; q++) acc[mt][nt][q] = 0.f;

    #define XH(s) (gsm + (s) * STG)
    #define XL(s) (gsm + (s) * STG + SX)
    #define WH(s) (gsm + (s) * STG + 2 * SX)
    #define WL(s) (gsm + (s) * STG + 2 * SX + SW)

    #define LOAD_STAGE(s, kc) do {                                            \
        _Pragma("unroll")                                                      \
        for (int rr = 0; rr < MT; rr++) {                                      \
            cp16(smem_u32(XH(s) + (lr + 64 * rr) * GSTR + lch),                \
                 Xh + (size_t)(bm + lr + 64 * rr) * C + (kc) + lch);           \
            cp16(smem_u32(XL(s) + (lr + 64 * rr) * GSTR + lch),                \
                 Xl + (size_t)(bm + lr + 64 * rr) * C + (kc) + lch);           \
        }                                                                      \
        _Pragma("unroll")                                                      \
        for (int rr = 0; rr < 2; rr++) {                                       \
            cp16(smem_u32(WH(s) + (lr + 64 * rr) * GSTR + lch),                \
                 Wh + (size_t)(bn + lr + 64 * rr) * C + (kc) + lch);           \
            cp16(smem_u32(WL(s) + (lr + 64 * rr) * GSTR + lch),                \
                 Wl + (size_t)(bn + lr + 64 * rr) * C + (kc) + lch);           \
        }                                                                      \
    } while (0)

    LOAD_STAGE(0, 0);
    CP_COMMIT();

    #pragma unroll
    for (int kk = 0; kk < 8; kk++) {
        int s = kk & 1;
        if (kk < 7) {
            LOAD_STAGE(s ^ 1, (kk + 1) * 32);
            CP_COMMIT();
            CP_WAIT(1);
        } else {
            CP_WAIT(0);
        }
        __syncthreads();

        #pragma unroll
        for (int ks = 0; ks < 2; ks++) {
            int acol = ks * 16 + (lane >> 4) * 8;
            int arow = wm + (lane & 15);
            unsigned ah[MT][4], al[MT][4];
            #pragma unroll
            for (int mt = 0; mt < MT; mt++) {
                ldmx4(ah[mt], smem_u32(XH(s) + (arow + mt * 16) * GSTR + acol));
                ldmx4(al[mt], smem_u32(XL(s) + (arow + mt * 16) * GSTR + acol));
            }
            unsigned bh[8][2], bl[8][2];
            #pragma unroll
            for (int nt4 = 0; nt4 < 4; nt4++) {
                int brow = wn + nt4 * 16 + (lane & 15);
                unsigned t[4];
                ldmx4(t, smem_u32(WH(s) + brow * GSTR + acol));
                bh[nt4 * 2][0] = t[0]; bh[nt4 * 2][1] = t[2];
                bh[nt4 * 2 + 1][0] = t[1]; bh[nt4 * 2 + 1][1] = t[3];
                ldmx4(t, smem_u32(WL(s) + brow * GSTR + acol));
                bl[nt4 * 2][0] = t[0]; bl[nt4 * 2][1] = t[2];
                bl[nt4 * 2 + 1][0] = t[1]; bl[nt4 * 2 + 1][1] = t[3];
            }
            #pragma unroll
            for (int mt = 0; mt < MT; mt++)
                #pragma unroll
                for (int nt = 0; nt < 8; nt++) {
                    mma_bf16(acc[mt][nt], ah[mt], bh[nt][0], bh[nt][1]);
                    mma_bf16(acc[mt][nt], ah[mt], bl[nt][0], bl[nt][1]);
                    mma_bf16(acc[mt][nt], al[mt], bh[nt][0], bh[nt][1]);
                }
        }
        __syncthreads();
    }

    int r_in = (lane >> 2), c_in = (lane & 3) * 2;
    #pragma unroll
    for (int mt = 0; mt < MT; mt++)
        #pragma unroll
        for (int nt = 0; nt < 8; nt++) {
            int col = bn + wn + nt * 8 + c_in;
            float b0 = bias[col], b1 = bias[col + 1];
            int row0 = bm + wm + mt * 16 + r_in;
            float s00 = (acc[mt][nt][0] + b0) * scale;
            float s01 = (acc[mt][nt][1] + b1) * scale;
            float s10 = (acc[mt][nt][2] + b0) * scale;
            float s11 = (acc[mt][nt][3] + b1) * scale;
            __half* dst;
            size_t i0;
            if (EPI == 0 || col < C) {
                dst = O1;
                i0 = (size_t)row0 * C + col;
            } else {
                dst = O2;
                i0 = (size_t)row0 * C + (col - C);
            }
            *(__half2*)(dst + i0) =
                __half2(__float2half_rn(s00), __float2half_rn(s01));
            *(__half2*)(dst + i0 + 8 * C) =
                __half2(__float2half_rn(s10), __float2half_rn(s11));
        }
    #undef LOAD_STAGE
    #undef XH
    #undef XL
    #undef WH
    #undef WL
}

// ---------------- SR conv + fused x split (re-read, 2 channels/thread) --------
__global__ __launch_bounds__(128) void srconv_kernel(
    const float* __restrict__ x,
    const float* __restrict__ g1, const float* __restrict__ b1,
    const float* __restrict__ m1, const float* __restrict__ v1,
    const float* __restrict__ w2,
    const float* __restrict__ g2, const float* __restrict__ b2,
    const float* __restrict__ m2, const float* __restrict__ v2) {
    int opix = blockIdx.x;
    int b = blockIdx.y;
    int c = threadIdx.x * 2;
    int oy = opix >> 4, ox = opix & 15;
    const float* xb = x + (size_t)b * NPIX * C;
    float s0 = 0.f, s1 = 0.f;

    if (oy >= 1 && ox >= 1) {
        const float* base = xb + (size_t)((oy * 4 - 3) * WIMG + ox * 4 - 3) * C + c;
        #pragma unroll
        for (int ky = 0; ky < 7; ky++) {
            #pragma unroll
            for (int kx = 0; kx < 7; kx++) {
                float2 v = *(const float2*)(base + (size_t)(ky * WIMG + kx) * C);
                float2 wv = *(const float2*)(g_w7t + (ky * 7 + kx) * C + c);
                s0 += v.x * wv.x;
                s1 += v.y * wv.y;
            }
        }
    } else {
        #pragma unroll
        for (int ky = 0; ky < 7; ky++) {
            int iy = oy * 4 - 3 + ky;
            if (iy < 0) continue;
            #pragma unroll
            for (int kx = 0; kx < 7; kx++) {
                int ix = ox * 4 - 3 + kx;
                if (ix < 0) continue;
                float2 v = *(const float2*)(xb + (size_t)(iy * WIMG + ix) * C + c);
                float2 wv = *(const float2*)(g_w7t + (ky * 7 + kx) * C + c);
                s0 += v.x * wv.x;
                s1 += v.y * wv.y;
            }
        }
    }

    // fused x hi/lo split: re-read the 16 owned pixels (L2-hot), split-store
    {
        size_t pbase = (size_t)b * NPIX * C;
        #pragma unroll
        for (int p = 0; p < 16; p++) {
            int ip = (oy * 4 + (p >> 2)) * WIMG + ox * 4 + (p & 3);
            size_t idx = (size_t)ip * C + c;
            float2 v = *(const float2*)(xb + idx);
            split_store(g_xh, g_xl, pbase + idx, v.x, v.y);
        }
    }

    float sc1a = g1[c] * rsqrtf(v1[c] + EPS);
    float sc1b = g1[c + 1] * rsqrtf(v1[c + 1] + EPS);
    float va = s0 * sc1a + (b1[c] - m1[c] * sc1a);
    float vb = s1 * sc1b + (b1[c + 1] - m1[c + 1] * sc1b);
    va = 0.5f * va * (1.f + erff(va * 0.7071067811865476f));
    vb = 0.5f * vb * (1.f + erff(vb * 0.7071067811865476f));
    va *= w2[c];
    vb *= w2[c + 1];
    float sc2a = g2[c] * rsqrtf(v2[c] + EPS);
    float sc2b = g2[c + 1] * rsqrtf(v2[c + 1] + EPS);
    va = va * sc2a + (b2[c] - m2[c] * sc2a);
    vb = vb * sc2b + (b2[c + 1] - m2[c + 1] * sc2b);
    *(float2*)(g_kvred + ((size_t)b * MRED + opix) * C + c) = make_float2(va, vb);
}

// ---------------- local 3x3 dwconv + residual -> bf16 hi/lo -------------------
__global__ __launch_bounds__(128) void localconv_kernel(
    const float* __restrict__ lb) {
    int opix = blockIdx.x;
    int b = blockIdx.y;
    int c = threadIdx.x * 2;
    int y = opix >> 4, xq = opix & 15;
    const float* src = g_kvred + (size_t)b * MRED * C;
    float2 ctr = *(const float2*)(src + (size_t)opix * C + c);
    float s0 = lb[c] + ctr.x;
    float s1 = lb[c + 1] + ctr.y;
    #pragma unroll
    for (int dy = -1; dy <= 1; dy++) {
        int yy = y + dy;
        if (yy < 0 || yy >= 16) continue;
        #pragma unroll
        for (int dx = -1; dx <= 1; dx++) {
            int xx = xq + dx;
            if (xx < 0 || xx >= 16) continue;
            float2 wv = *(const float2*)(g_lwt + ((dy + 1) * 3 + (dx + 1)) * C + c);
            float2 sv = *(const float2*)(src + (size_t)(yy * 16 + xx) * C + c);
            s0 += sv.x * wv.x;
            s1 += sv.y * wv.y;
        }
    }
    split_store(g_kv2h, g_kv2l, ((size_t)b * MRED + opix) * C + c, s0, s1);
}

// ---------------- flash attention via mma.sync fp16 (no split) ----------------
#define QSTR 40
#define VSTR 264
#define SM_KF 0
#define SM_VT (SM_KF + 256 * QSTR)
#define ATTN_SMEM ((SM_VT + 32 * VSTR) * 2)

__global__ __launch_bounds__(256, 2) void attn_kernel(float* __restrict__ out) {
    extern __shared__ __half smf[];
    __half* kf = smf + SM_KF;
    __half* vt = smf + SM_VT;

    int tid = threadIdx.x, lane = tid & 31, w = tid >> 5;
    int head = blockIdx.y, b = blockIdx.z;

    for (int i = tid; i < 1024; i += 256) {
        int m = i >> 2, ch = (i & 3) * 8;
        size_t src = (size_t)(b * MRED + m) * C + head * HD + ch;
        *(uint4*)(kf + m * QSTR + ch) = *(const uint4*)(g_kf + src);
    }
    for (int i = tid; i < 256 * 16; i += 256) {
        int m = i >> 4, d2 = (i & 15) * 2;
        __half2 v = *(const __half2*)(
            g_vf + (size_t)(b * MRED + m) * C + head * HD + d2);
        vt[d2 * VSTR + m] = v.x;
        vt[(d2 + 1) * VSTR + m] = v.y;
    }
    __syncthreads();

    int m0 = w * 16;

    #pragma unroll 1
    for (int qq = 0; qq < 4; qq++) {
        int qtile = blockIdx.x * 4 + qq;

        unsigned qf[2][4];
        {
            size_t qbase = (size_t)(b * NPIX + qtile * 128 + m0 + (lane >> 2)) * C
                           + head * HD + (lane & 3) * 2;
            #pragma unroll
            for (int kt = 0; kt < 2; kt++) {
                size_t o0 = qbase + kt * 16;
                qf[kt][0] = *(const unsigned*)(g_qf + o0);
                qf[kt][1] = *(const unsigned*)(g_qf + o0 + 8 * C);
                qf[kt][2] = *(const unsigned*)(g_qf + o0 + 8);
                qf[kt][3] = *(const unsigned*)(g_qf + o0 + 8 * C + 8);
            }
        }

        float m_lo = -1e30f, m_hi = -1e30f, sum_lo = 0.f, sum_hi = 0.f;
        float o[4][4];
        #pragma unroll
        for (int i = 0; i < 4; i++)
            #pragma unroll
            for (int j = 0; j < 4; j++) o[i][j] = 0.f;

        #pragma unroll
        for (int kb = 0; kb < 4; kb++) {
            float s[8][4];
            #pragma unroll
            for (int j = 0; j < 8; j++)
                #pragma unroll
                for (int q = 0; q < 4; q++) s[j][q] = 0.f;
            #pragma unroll
            for (int kt = 0; kt < 2; kt++) {
                int col = kt * 16 + (lane >> 4) * 8;
                #pragma unroll
                for (int jj = 0; jj < 4; jj++) {
                    int row = kb * 64 + jj * 16 + (lane & 15);
                    unsigned t[4];
                    ldmx4(t, smem_u32(kf + row * QSTR + col));
                    mma_fp16(s[2 * jj], qf[kt], t[0], t[2]);
                    mma_fp16(s[2 * jj + 1], qf[kt], t[1], t[3]);
                }
            }
            float bm_lo = -1e30f, bm_hi = -1e30f;
            #pragma unroll
            for (int j = 0; j < 8; j++) {
                bm_lo = fmaxf(bm_lo, fmaxf(s[j][0], s[j][1]));
                bm_hi = fmaxf(bm_hi, fmaxf(s[j][2], s[j][3]));
            }
            bm_lo = fmaxf(bm_lo, __shfl_xor_sync(0xFFFFFFFFu, bm_lo, 1));
            bm_lo = fmaxf(bm_lo, __shfl_xor_sync(0xFFFFFFFFu, bm_lo, 2));
            bm_hi = fmaxf(bm_hi, __shfl_xor_sync(0xFFFFFFFFu, bm_hi, 1));
            bm_hi = fmaxf(bm_hi, __shfl_xor_sync(0xFFFFFFFFu, bm_hi, 2));
            float nm_lo = fmaxf(m_lo, bm_lo);
            float nm_hi = fmaxf(m_hi, bm_hi);
            float corr_lo = exp2f(m_lo - nm_lo);
            float corr_hi = exp2f(m_hi - nm_hi);
            m_lo = nm_lo; m_hi = nm_hi;
            sum_lo *= corr_lo; sum_hi *= corr_hi;
            #pragma unroll
            for (int dn = 0; dn < 4; dn++) {
                o[dn][0] *= corr_lo; o[dn][1] *= corr_lo;
                o[dn][2] *= corr_hi; o[dn][3] *= corr_hi;
            }
            unsigned pl[8], ph[8];
            #pragma unroll
            for (int j = 0; j < 8; j++) {
                float p0 = exp2f(s[j][0] - m_lo);
                float p1 = exp2f(s[j][1] - m_lo);
                float p2 = exp2f(s[j][2] - m_hi);
                float p3 = exp2f(s[j][3] - m_hi);
                sum_lo += p0 + p1;
                sum_hi += p2 + p3;
                pl[j] = pack_f16x2(p0, p1);
                ph[j] = pack_f16x2(p2, p3);
            }
            #pragma unroll
            for (int kt = 0; kt < 4; kt++) {
                unsigned a[4] = {pl[2 * kt], ph[2 * kt],
                                 pl[2 * kt + 1], ph[2 * kt + 1]};
                int kcol = kb * 64 + kt * 16 + (lane >> 4) * 8;
                #pragma unroll
                for (int dn2 = 0; dn2 < 2; dn2++) {
                    int drow = dn2 * 16 + (lane & 15);
                    unsigned t[4];
                    ldmx4(t, smem_u32(vt + drow * VSTR + kcol));
                    mma_fp16(o[2 * dn2], a, t[0], t[2]);
                    mma_fp16(o[2 * dn2 + 1], a, t[1], t[3]);
                }
            }
        }

        sum_lo += __shfl_xor_sync(0xFFFFFFFFu, sum_lo, 1);
        sum_lo += __shfl_xor_sync(0xFFFFFFFFu, sum_lo, 2);
        sum_hi += __shfl_xor_sync(0xFFFFFFFFu, sum_hi, 1);
        sum_hi += __shfl_xor_sync(0xFFFFFFFFu, sum_hi, 2);
        float inv_lo = 1.f / sum_lo;
        float inv_hi = 1.f / sum_hi;
        int r = lane >> 2, cc = (lane & 3) * 2;
        int q0 = qtile * 128 + m0 + r;
        #pragma unroll
        for (int dn = 0; dn < 4; dn++) {
            int d = dn * 8 + cc;
            float2 t0 = make_float2(o[dn][0] * inv_lo, o[dn][1] * inv_lo);
            float2 t1 = make_float2(o[dn][2] * inv_hi, o[dn][3] * inv_hi);
            *(float2*)(out + ((size_t)(b * NPIX + q0)) * C + head * HD + d) = t0;
            *(float2*)(out + ((size_t)(b * NPIX + q0 + 8)) * C + head * HD + d) = t1;
        }
    }
}

// ---------------- launch ------------------------------------------------------
extern "C" void kernel_launch(void* const* d_in, const int* in_sizes, int n_in,
                              void* d_out, int out_size) {
    int base = (n_in >= 19) ? 3 : 1;
    const float* x      = (const float*)d_in[0];
    const float* Wq     = (const float*)d_in[base + 0];
    const float* bq     = (const float*)d_in[base + 1];
    const float* Wkv    = (const float*)d_in[base + 2];
    const float* bkv    = (const float*)d_in[base + 3];
    const float* sr_w1  = (const float*)d_in[base + 4];
    const float* bn1g   = (const float*)d_in[base + 5];
    const float* bn1b   = (const float*)d_in[base + 6];
    const float* bn1m   = (const float*)d_in[base + 7];
    const float* bn1v   = (const float*)d_in[base + 8];
    const float* sr_w2  = (const float*)d_in[base + 9];
    const float* bn2g   = (const float*)d_in[base + 10];
    const float* bn2b   = (const float*)d_in[base + 11];
    const float* bn2m   = (const float*)d_in[base + 12];
    const float* bn2v   = (const float*)d_in[base + 13];
    const float* lw     = (const float*)d_in[base + 14];
    const float* lb     = (const float*)d_in[base + 15];
    float* out = (float*)d_out;

    __nv_bfloat16 *xh, *xl, *wqh, *wql, *wkvh, *wkvl, *kv2h, *kv2l;
    __half *qf, *kfp, *vfp;
    cudaGetSymbolAddress((void**)&xh, g_xh);
    cudaGetSymbolAddress((void**)&xl, g_xl);
    cudaGetSymbolAddress((void**)&wqh, g_wqh);
    cudaGetSymbolAddress((void**)&wql, g_wql);
    cudaGetSymbolAddress((void**)&wkvh, g_wkvh);
    cudaGetSymbolAddress((void**)&wkvl, g_wkvl);
    cudaGetSymbolAddress((void**)&kv2h, g_kv2h);
    cudaGetSymbolAddress((void**)&kv2l, g_kv2l);
    cudaGetSymbolAddress((void**)&qf, g_qf);
    cudaGetSymbolAddress((void**)&kfp, g_kf);
    cudaGetSymbolAddress((void**)&vfp, g_vf);

    const int smem128 = 2 * (2 * 128 * GSTR + 2 * 128 * GSTR) * 2;  // 81920
    const int smem64  = 2 * (2 * 64 * GSTR + 2 * 128 * GSTR) * 2;   // 61440
    cudaFuncSetAttribute((const void*)gemm_mma_kernel<128, 0>,
                         cudaFuncAttributeMaxDynamicSharedMemorySize, smem128);
    cudaFuncSetAttribute((const void*)gemm_mma_kernel<64, 1>,
                         cudaFuncAttributeMaxDynamicSharedMemorySize, smem64);
    cudaFuncSetAttribute((const void*)attn_kernel,
                         cudaFuncAttributeMaxDynamicSharedMemorySize, ATTN_SMEM);

    const float QSC = ATTN_SCALE * 1.4426950408889634f;

    prep_weights_kernel<<<192 + 49, 256>>>(Wq, Wkv, sr_w1, lw);
    srconv_kernel<<<dim3(MRED, BATCH), 128>>>(x, bn1g, bn1b, bn1m, bn1v,
                                              sr_w2, bn2g, bn2b, bn2m, bn2v);
    localconv_kernel<<<dim3(MRED, BATCH), 128>>>(lb);
    gemm_mma_kernel<64, 1><<<dim3(2 * C / 128, BATCH * MRED / 64), 256, smem64>>>(
        kv2h, kv2l, wkvh, wkvl, bkv, kfp, vfp, 1.0f);
    gemm_mma_kernel<128, 0><<<dim3(C / 128, BATCH * NPIX / 128), 256, smem128>>>(
        xh, xl, wqh, wql, bq, qf, nullptr, QSC);
    attn_kernel<<<dim3(NPIX / 512, HEADS, BATCH), 256, ATTN_SMEM>>>(out);
}

// round 16
// speedup vs baseline: 1.9651x; 1.3652x over previous
#include <cuda_runtime.h>
#include <cuda_fp16.h>
#include <math.h>
#include <string.h>

#define BATCH 8
#define C 256
#define NPIX 4096
#define HIMG 64
#define WIMG 64
#define MRED 256
#define HEADS 8
#define HD 32
#define ATTN_SCALE 0.17677669529663687f
#define EPS 1e-5f

// ---------------- scratch ----------------------------------------------------
__device__ float g_kvred[BATCH * MRED * C];   // (b, m, c)
__device__ __half g_xf[BATCH * NPIX * C];     // x fp16
__device__ __half g_wqf[C * C];
__device__ __half g_wkvf[2 * C * C];
__device__ __half g_kv2f[BATCH * MRED * C];
__device__ __half g_qf[BATCH * NPIX * C];     // pre-scaled q
__device__ __half g_kf[BATCH * MRED * C];
__device__ __half g_vf[BATCH * MRED * C];
__device__ float g_w7t[49 * C];
__device__ float g_lwt[9 * C];

// ---------------- helpers ------------------------------------------------------
__device__ __forceinline__ unsigned smem_u32(const void* p) {
    unsigned a;
    asm("{ .reg .u64 t; cvta.to.shared.u64 t, %1; cvt.u32.u64 %0, t; }"
        : "=r"(a) : "l"(p));
    return a;
}
__device__ __forceinline__ void cp16(unsigned dst, const void* src) {
    asm volatile("cp.async.ca.shared.global [%0], [%1], 16;"
                 :: "r"(dst), "l"(src));
}
#define CP_COMMIT() asm volatile("cp.async.commit_group;" ::: "memory")
#define CP_WAIT(n)  asm volatile("cp.async.wait_group %0;" :: "n"(n) : "memory")

__device__ __forceinline__ void ldmx4(unsigned* r, unsigned addr) {
    asm volatile("ldmatrix.sync.aligned.m8n8.x4.shared.b16 {%0,%1,%2,%3}, [%4];"
                 : "=r"(r[0]), "=r"(r[1]), "=r"(r[2]), "=r"(r[3]) : "r"(addr));
}
__device__ __forceinline__ void mma_fp16(float* c, const unsigned* a,
                                         unsigned b0, unsigned b1) {
    asm volatile(
        "mma.sync.aligned.m16n8k16.row.col.f32.f16.f16.f32 "
        "{%0,%1,%2,%3}, {%4,%5,%6,%7}, {%8,%9}, {%0,%1,%2,%3};"
        : "+f"(c[0]), "+f"(c[1]), "+f"(c[2]), "+f"(c[3])
        : "r"(a[0]), "r"(a[1]), "r"(a[2]), "r"(a[3]), "r"(b0), "r"(b1));
}
__device__ __forceinline__ unsigned pack_f16x2(float lo, float hi) {
    unsigned d;
    asm("cvt.rn.f16x2.f32 %0, %1, %2;" : "=r"(d) : "f"(hi), "f"(lo));
    return d;
}

// ---------------- weights prep: Wq/Wkv -> fp16 + conv-weight transpose --------
__global__ __launch_bounds__(256) void prep_weights_kernel(
    const float* __restrict__ Wq, const float* __restrict__ Wkv,
    const float* __restrict__ w7, const float* __restrict__ lw) {
    int bx = blockIdx.x, tid = threadIdx.x;
    if (bx < 64) {
        int i = bx * 256 + tid;
        float4 v = ((const float4*)Wq)[i];
        uint2 o;
        o.x = pack_f16x2(v.x, v.y);
        o.y = pack_f16x2(v.z, v.w);
        ((uint2*)g_wqf)[i] = o;
    } else if (bx < 192) {
        int i = (bx - 64) * 256 + tid;
        float4 v = ((const float4*)Wkv)[i];
        uint2 o;
        o.x = pack_f16x2(v.x, v.y);
        o.y = pack_f16x2(v.z, v.w);
        ((uint2*)g_wkvf)[i] = o;
    } else {
        int k = bx - 192;
        g_w7t[k * C + tid] = w7[tid * 49 + k];
        if (k < 9) g_lwt[k * C + tid] = lw[tid * 9 + k];
    }
}

// ---------------- HMMA GEMM fp16 + cp.async double buffer ---------------------
#define GSTR 40
template <int BM, int EPI>
__global__ __launch_bounds__(256, 2) void gemm_mma_kernel(
    const __half* __restrict__ Xf, const __half* __restrict__ Wf,
    const float* __restrict__ bias,
    __half* __restrict__ O1, __half* __restrict__ O2, float scale) {
    constexpr int MT = BM / 64;
    constexpr int SX = BM * GSTR;
    constexpr int SW = 128 * GSTR;
    constexpr int STG = SX + SW;
    extern __shared__ __half gsm[];

    int tid = threadIdx.x, lane = tid & 31, w = tid >> 5;
    int bm = blockIdx.y * BM, bn = blockIdx.x * 128;
    int wm = (w & 3) * (16 * MT), wn = (w >> 2) * 64;
    int lr = tid >> 2, lch = (tid & 3) * 8;

    float acc[MT][8][4];
    #pragma unroll
    for (int mt = 0; mt < MT; mt++)
        #pragma unroll
        for (int nt = 0; nt < 8; nt++)
            #pragma unroll
            for (int q = 0; q < 4; q++) acc[mt][nt][q] = 0.f;

    #define XS(s) (gsm + (s) * STG)
    #define WS(s) (gsm + (s) * STG + SX)

    #define LOAD_STAGE(s, kc) do {                                            \
        _Pragma("unroll")                                                      \
        for (int rr = 0; rr < MT; rr++)                                        \
            cp16(smem_u32(XS(s) + (lr + 64 * rr) * GSTR + lch),                \
                 Xf + (size_t)(bm + lr + 64 * rr) * C + (kc) + lch);           \
        _Pragma("unroll")                                                      \
        for (int rr = 0; rr < 2; rr++)                                         \
            cp16(smem_u32(WS(s) + (lr + 64 * rr) * GSTR + lch),                \
                 Wf + (size_t)(bn + lr + 64 * rr) * C + (kc) + lch);           \
    } while (0)

    LOAD_STAGE(0, 0);
    CP_COMMIT();

    #pragma unroll
    for (int kk = 0; kk < 8; kk++) {
        int s = kk & 1;
        if (kk < 7) {
            LOAD_STAGE(s ^ 1, (kk + 1) * 32);
            CP_COMMIT();
            CP_WAIT(1);
        } else {
            CP_WAIT(0);
        }
        __syncthreads();

        #pragma unroll
        for (int ks = 0; ks < 2; ks++) {
            int acol = ks * 16 + (lane >> 4) * 8;
            int arow = wm + (lane & 15);
            unsigned af[MT][4];
            #pragma unroll
            for (int mt = 0; mt < MT; mt++)
                ldmx4(af[mt], smem_u32(XS(s) + (arow + mt * 16) * GSTR + acol));
            unsigned bf[8][2];
            #pragma unroll
            for (int nt4 = 0; nt4 < 4; nt4++) {
                int brow = wn + nt4 * 16 + (lane & 15);
                unsigned t[4];
                ldmx4(t, smem_u32(WS(s) + brow * GSTR + acol));
                bf[nt4 * 2][0] = t[0]; bf[nt4 * 2][1] = t[2];
                bf[nt4 * 2 + 1][0] = t[1]; bf[nt4 * 2 + 1][1] = t[3];
            }
            #pragma unroll
            for (int mt = 0; mt < MT; mt++)
                #pragma unroll
                for (int nt = 0; nt < 8; nt++)
                    mma_fp16(acc[mt][nt], af[mt], bf[nt][0], bf[nt][1]);
        }
        __syncthreads();
    }

    int r_in = (lane >> 2), c_in = (lane & 3) * 2;
    #pragma unroll
    for (int mt = 0; mt < MT; mt++)
        #pragma unroll
        for (int nt = 0; nt < 8; nt++) {
            int col = bn + wn + nt * 8 + c_in;
            float b0 = bias[col], b1 = bias[col + 1];
            int row0 = bm + wm + mt * 16 + r_in;
            float s00 = (acc[mt][nt][0] + b0) * scale;
            float s01 = (acc[mt][nt][1] + b1) * scale;
            float s10 = (acc[mt][nt][2] + b0) * scale;
            float s11 = (acc[mt][nt][3] + b1) * scale;
            __half* dst;
            size_t i0;
            if (EPI == 0 || col < C) {
                dst = O1;
                i0 = (size_t)row0 * C + col;
            } else {
                dst = O2;
                i0 = (size_t)row0 * C + (col - C);
            }
            *(unsigned*)(dst + i0) = pack_f16x2(s00, s01);
            *(unsigned*)(dst + i0 + 8 * C) = pack_f16x2(s10, s11);
        }
    #undef LOAD_STAGE
    #undef XS
    #undef WS
}

// ---------------- SR conv + fused x fp16 convert (L2 re-read) -----------------
__global__ __launch_bounds__(128) void srconv_kernel(
    const float* __restrict__ x,
    const float* __restrict__ g1, const float* __restrict__ b1,
    const float* __restrict__ m1, const float* __restrict__ v1,
    const float* __restrict__ w2,
    const float* __restrict__ g2, const float* __restrict__ b2,
    const float* __restrict__ m2, const float* __restrict__ v2) {
    int opix = blockIdx.x;
    int b = blockIdx.y;
    int c = threadIdx.x * 2;
    int oy = opix >> 4, ox = opix & 15;
    const float* xb = x + (size_t)b * NPIX * C;
    float s0 = 0.f, s1 = 0.f;

    if (oy >= 1 && ox >= 1) {   // interior: high side never clips (15*4+3 = 63)
        const float* base = xb + (size_t)((oy * 4 - 3) * WIMG + ox * 4 - 3) * C + c;
        #pragma unroll
        for (int ky = 0; ky < 7; ky++) {
            #pragma unroll
            for (int kx = 0; kx < 7; kx++) {
                float2 v = *(const float2*)(base + (size_t)(ky * WIMG + kx) * C);
                float2 wv = *(const float2*)(g_w7t + (ky * 7 + kx) * C + c);
                s0 += v.x * wv.x;
                s1 += v.y * wv.y;
            }
        }
    } else {
        #pragma unroll
        for (int ky = 0; ky < 7; ky++) {
            int iy = oy * 4 - 3 + ky;
            if (iy < 0) continue;
            #pragma unroll
            for (int kx = 0; kx < 7; kx++) {
                int ix = ox * 4 - 3 + kx;
                if (ix < 0) continue;
                float2 v = *(const float2*)(xb + (size_t)(iy * WIMG + ix) * C + c);
                float2 wv = *(const float2*)(g_w7t + (ky * 7 + kx) * C + c);
                s0 += v.x * wv.x;
                s1 += v.y * wv.y;
            }
        }
    }

    // fused x -> fp16: re-read the 16 owned pixels (L2-hot), convert-store
    {
        size_t pbase = (size_t)b * NPIX * C;
        #pragma unroll
        for (int p = 0; p < 16; p++) {
            int ip = (oy * 4 + (p >> 2)) * WIMG + ox * 4 + (p & 3);
            size_t idx = (size_t)ip * C + c;
            float2 v = *(const float2*)(xb + idx);
            *(unsigned*)(g_xf + pbase + idx) = pack_f16x2(v.x, v.y);
        }
    }

    float sc1a = g1[c] * rsqrtf(v1[c] + EPS);
    float sc1b = g1[c + 1] * rsqrtf(v1[c + 1] + EPS);
    float va = s0 * sc1a + (b1[c] - m1[c] * sc1a);
    float vb = s1 * sc1b + (b1[c + 1] - m1[c + 1] * sc1b);
    va = 0.5f * va * (1.f + erff(va * 0.7071067811865476f));
    vb = 0.5f * vb * (1.f + erff(vb * 0.7071067811865476f));
    va *= w2[c];
    vb *= w2[c + 1];
    float sc2a = g2[c] * rsqrtf(v2[c] + EPS);
    float sc2b = g2[c + 1] * rsqrtf(v2[c + 1] + EPS);
    va = va * sc2a + (b2[c] - m2[c] * sc2a);
    vb = vb * sc2b + (b2[c + 1] - m2[c + 1] * sc2b);
    *(float2*)(g_kvred + ((size_t)b * MRED + opix) * C + c) = make_float2(va, vb);
}

// ---------------- local 3x3 dwconv + residual -> fp16 --------------------------
__global__ __launch_bounds__(128) void localconv_kernel(
    const float* __restrict__ lb) {
    int opix = blockIdx.x;
    int b = blockIdx.y;
    int c = threadIdx.x * 2;
    int y = opix >> 4, xq = opix & 15;
    const float* src = g_kvred + (size_t)b * MRED * C;
    float2 ctr = *(const float2*)(src + (size_t)opix * C + c);
    float s0 = lb[c] + ctr.x;
    float s1 = lb[c + 1] + ctr.y;
    #pragma unroll
    for (int dy = -1; dy <= 1; dy++) {
        int yy = y + dy;
        if (yy < 0 || yy >= 16) continue;
        #pragma unroll
        for (int dx = -1; dx <= 1; dx++) {
            int xx = xq + dx;
            if (xx < 0 || xx >= 16) continue;
            float2 wv = *(const float2*)(g_lwt + ((dy + 1) * 3 + (dx + 1)) * C + c);
            float2 sv = *(const float2*)(src + (size_t)(yy * 16 + xx) * C + c);
            s0 += sv.x * wv.x;
            s1 += sv.y * wv.y;
        }
    }
    *(unsigned*)(g_kv2f + ((size_t)b * MRED + opix) * C + c) = pack_f16x2(s0, s1);
}

// ---------------- flash attention via mma.sync fp16 ----------------------------
#define QSTR 40
#define VSTR 264
#define SM_KF 0
#define SM_VT (SM_KF + 256 * QSTR)
#define ATTN_SMEM ((SM_VT + 32 * VSTR) * 2)

__global__ __launch_bounds__(256, 2) void attn_kernel(float* __restrict__ out) {
    extern __shared__ __half smf[];
    __half* kf = smf + SM_KF;
    __half* vt = smf + SM_VT;

    int tid = threadIdx.x, lane = tid & 31, w = tid >> 5;
    int head = blockIdx.y, b = blockIdx.z;

    for (int i = tid; i < 1024; i += 256) {
        int m = i >> 2, ch = (i & 3) * 8;
        size_t src = (size_t)(b * MRED + m) * C + head * HD + ch;
        *(uint4*)(kf + m * QSTR + ch) = *(const uint4*)(g_kf + src);
    }
    for (int i = tid; i < 256 * 16; i += 256) {
        int m = i >> 4, d2 = (i & 15) * 2;
        __half2 v = *(const __half2*)(
            g_vf + (size_t)(b * MRED + m) * C + head * HD + d2);
        vt[d2 * VSTR + m] = v.x;
        vt[(d2 + 1) * VSTR + m] = v.y;
    }
    __syncthreads();

    int m0 = w * 16;

    #pragma unroll 1
    for (int qq = 0; qq < 4; qq++) {
        int qtile = blockIdx.x * 4 + qq;

        unsigned qf[2][4];
        {
            size_t qbase = (size_t)(b * NPIX + qtile * 128 + m0 + (lane >> 2)) * C
                           + head * HD + (lane & 3) * 2;
            #pragma unroll
            for (int kt = 0; kt < 2; kt++) {
                size_t o0 = qbase + kt * 16;
                qf[kt][0] = *(const unsigned*)(g_qf + o0);
                qf[kt][1] = *(const unsigned*)(g_qf + o0 + 8 * C);
                qf[kt][2] = *(const unsigned*)(g_qf + o0 + 8);
                qf[kt][3] = *(const unsigned*)(g_qf + o0 + 8 * C + 8);
            }
        }

        float m_lo = -1e30f, m_hi = -1e30f, sum_lo = 0.f, sum_hi = 0.f;
        float o[4][4];
        #pragma unroll
        for (int i = 0; i < 4; i++)
            #pragma unroll
            for (int j = 0; j < 4; j++) o[i][j] = 0.f;

        #pragma unroll
        for (int kb = 0; kb < 4; kb++) {
            float s[8][4];
            #pragma unroll
            for (int j = 0; j < 8; j++)
                #pragma unroll
                for (int q = 0; q < 4; q++) s[j][q] = 0.f;
            #pragma unroll
            for (int kt = 0; kt < 2; kt++) {
                int col = kt * 16 + (lane >> 4) * 8;
                #pragma unroll
                for (int jj = 0; jj < 4; jj++) {
                    int row = kb * 64 + jj * 16 + (lane & 15);
                    unsigned t[4];
                    ldmx4(t, smem_u32(kf + row * QSTR + col));
                    mma_fp16(s[2 * jj], qf[kt], t[0], t[2]);
                    mma_fp16(s[2 * jj + 1], qf[kt], t[1], t[3]);
                }
            }
            float bm_lo = -1e30f, bm_hi = -1e30f;
            #pragma unroll
            for (int j = 0; j < 8; j++) {
                bm_lo = fmaxf(bm_lo, fmaxf(s[j][0], s[j][1]));
                bm_hi = fmaxf(bm_hi, fmaxf(s[j][2], s[j][3]));
            }
            bm_lo = fmaxf(bm_lo, __shfl_xor_sync(0xFFFFFFFFu, bm_lo, 1));
            bm_lo = fmaxf(bm_lo, __shfl_xor_sync(0xFFFFFFFFu, bm_lo, 2));
            bm_hi = fmaxf(bm_hi, __shfl_xor_sync(0xFFFFFFFFu, bm_hi, 1));
            bm_hi = fmaxf(bm_hi, __shfl_xor_sync(0xFFFFFFFFu, bm_hi, 2));
            float nm_lo = fmaxf(m_lo, bm_lo);
            float nm_hi = fmaxf(m_hi, bm_hi);
            float corr_lo = exp2f(m_lo - nm_lo);
            float corr_hi = exp2f(m_hi - nm_hi);
            m_lo = nm_lo; m_hi = nm_hi;
            sum_lo *= corr_lo; sum_hi *= corr_hi;
            #pragma unroll
            for (int dn = 0; dn < 4; dn++) {
                o[dn][0] *= corr_lo; o[dn][1] *= corr_lo;
                o[dn][2] *= corr_hi; o[dn][3] *= corr_hi;
            }
            unsigned pl[8], ph[8];
            #pragma unroll
            for (int j = 0; j < 8; j++) {
                float p0 = exp2f(s[j][0] - m_lo);
                float p1 = exp2f(s[j][1] - m_lo);
                float p2 = exp2f(s[j][2] - m_hi);
                float p3 = exp2f(s[j][3] - m_hi);
                sum_lo += p0 + p1;
                sum_hi += p2 + p3;
                pl[j] = pack_f16x2(p0, p1);
                ph[j] = pack_f16x2(p2, p3);
            }
            #pragma unroll
            for (int kt = 0; kt < 4; kt++) {
                unsigned a[4] = {pl[2 * kt], ph[2 * kt],
                                 pl[2 * kt + 1], ph[2 * kt + 1]};
                int kcol = kb * 64 + kt * 16 + (lane >> 4) * 8;
                #pragma unroll
                for (int dn2 = 0; dn2 < 2; dn2++) {
                    int drow = dn2 * 16 + (lane & 15);
                    unsigned t[4];
                    ldmx4(t, smem_u32(vt + drow * VSTR + kcol));
                    mma_fp16(o[2 * dn2], a, t[0], t[2]);
                    mma_fp16(o[2 * dn2 + 1], a, t[1], t[3]);
                }
            }
        }

        sum_lo += __shfl_xor_sync(0xFFFFFFFFu, sum_lo, 1);
        sum_lo += __shfl_xor_sync(0xFFFFFFFFu, sum_lo, 2);
        sum_hi += __shfl_xor_sync(0xFFFFFFFFu, sum_hi, 1);
        sum_hi += __shfl_xor_sync(0xFFFFFFFFu, sum_hi, 2);
        float inv_lo = 1.f / sum_lo;
        float inv_hi = 1.f / sum_hi;
        int r = lane >> 2, cc = (lane & 3) * 2;
        int q0 = qtile * 128 + m0 + r;
        #pragma unroll
        for (int dn = 0; dn < 4; dn++) {
            int d = dn * 8 + cc;
            float2 t0 = make_float2(o[dn][0] * inv_lo, o[dn][1] * inv_lo);
            float2 t1 = make_float2(o[dn][2] * inv_hi, o[dn][3] * inv_hi);
            *(float2*)(out + ((size_t)(b * NPIX + q0)) * C + head * HD + d) = t0;
            *(float2*)(out + ((size_t)(b * NPIX + q0 + 8)) * C + head * HD + d) = t1;
        }
    }
}

// ---------------- launch ------------------------------------------------------
extern "C" void kernel_launch(void* const* d_in, const int* in_sizes, int n_in,
                              void* d_out, int out_size) {
    int base = (n_in >= 19) ? 3 : 1;
    const float* x      = (const float*)d_in[0];
    const float* Wq     = (const float*)d_in[base + 0];
    const float* bq     = (const float*)d_in[base + 1];
    const float* Wkv    = (const float*)d_in[base + 2];
    const float* bkv    = (const float*)d_in[base + 3];
    const float* sr_w1  = (const float*)d_in[base + 4];
    const float* bn1g   = (const float*)d_in[base + 5];
    const float* bn1b   = (const float*)d_in[base + 6];
    const float* bn1m   = (const float*)d_in[base + 7];
    const float* bn1v   = (const float*)d_in[base + 8];
    const float* sr_w2  = (const float*)d_in[base + 9];
    const float* bn2g   = (const float*)d_in[base + 10];
    const float* bn2b   = (const float*)d_in[base + 11];
    const float* bn2m   = (const float*)d_in[base + 12];
    const float* bn2v   = (const float*)d_in[base + 13];
    const float* lw     = (const float*)d_in[base + 14];
    const float* lb     = (const float*)d_in[base + 15];
    float* out = (float*)d_out;

    __half *xf, *wqf, *wkvf, *kv2f, *qf, *kfp, *vfp;
    cudaGetSymbolAddress((void**)&xf, g_xf);
    cudaGetSymbolAddress((void**)&wqf, g_wqf);
    cudaGetSymbolAddress((void**)&wkvf, g_wkvf);
    cudaGetSymbolAddress((void**)&kv2f, g_kv2f);
    cudaGetSymbolAddress((void**)&qf, g_qf);
    cudaGetSymbolAddress((void**)&kfp, g_kf);
    cudaGetSymbolAddress((void**)&vfp, g_vf);

    const int smem128 = 2 * (128 * GSTR + 128 * GSTR) * 2;  // 40960
    const int smem64  = 2 * (64 * GSTR + 128 * GSTR) * 2;   // 30720
    cudaFuncSetAttribute((const void*)gemm_mma_kernel<128, 0>,
                         cudaFuncAttributeMaxDynamicSharedMemorySize, smem128);
    cudaFuncSetAttribute((const void*)gemm_mma_kernel<64, 1>,
                         cudaFuncAttributeMaxDynamicSharedMemorySize, smem64);
    cudaFuncSetAttribute((const void*)attn_kernel,
                         cudaFuncAttributeMaxDynamicSharedMemorySize, ATTN_SMEM);

    const float QSC = ATTN_SCALE * 1.4426950408889634f;

    prep_weights_kernel<<<192 + 49, 256>>>(Wq, Wkv, sr_w1, lw);
    srconv_kernel<<<dim3(MRED, BATCH), 128>>>(x, bn1g, bn1b, bn1m, bn1v,
                                              sr_w2, bn2g, bn2b, bn2m, bn2v);
    localconv_kernel<<<dim3(MRED, BATCH), 128>>>(lb);
    gemm_mma_kernel<64, 1><<<dim3(2 * C / 128, BATCH * MRED / 64), 256, smem64>>>(
        kv2f, wkvf, bkv, kfp, vfp, 1.0f);
    gemm_mma_kernel<128, 0><<<dim3(C / 128, BATCH * NPIX / 128), 256, smem128>>>(
        xf, wqf, bq, qf, nullptr, QSC);
    attn_kernel<<<dim3(NPIX / 512, HEADS, BATCH), 256, ATTN_SMEM>>>(out);
}

// round 17
// speedup vs baseline: 2.0579x; 1.0473x over previous
#include <cuda_runtime.h>
#include <cuda_fp16.h>
#include <math.h>
#include <string.h>

#define BATCH 8
#define C 256
#define NPIX 4096
#define HIMG 64
#define WIMG 64
#define MRED 256
#define HEADS 8
#define HD 32
#define ATTN_SCALE 0.17677669529663687f
#define EPS 1e-5f

// ---------------- scratch ----------------------------------------------------
__device__ float g_kvred[BATCH * MRED * C];   // (b, m, c)
__device__ __half g_xf[BATCH * NPIX * C];     // x fp16
__device__ __half g_wqf[C * C];
__device__ __half g_wkvf[2 * C * C];
__device__ __half g_kv2f[BATCH * MRED * C];
__device__ __half g_qf[BATCH * NPIX * C];     // pre-scaled q
__device__ __half g_kf[BATCH * MRED * C];
__device__ __half g_vf[BATCH * MRED * C];
__device__ float g_w7t[49 * C];
__device__ float g_lwt[9 * C];

// ---------------- helpers ------------------------------------------------------
__device__ __forceinline__ unsigned smem_u32(const void* p) {
    unsigned a;
    asm("{ .reg .u64 t; cvta.to.shared.u64 t, %1; cvt.u32.u64 %0, t; }"
        : "=r"(a) : "l"(p));
    return a;
}
__device__ __forceinline__ void cp16(unsigned dst, const void* src) {
    asm volatile("cp.async.ca.shared.global [%0], [%1], 16;"
                 :: "r"(dst), "l"(src));
}
#define CP_COMMIT() asm volatile("cp.async.commit_group;" ::: "memory")
#define CP_WAIT(n)  asm volatile("cp.async.wait_group %0;" :: "n"(n) : "memory")

__device__ __forceinline__ void ldmx4(unsigned* r, unsigned addr) {
    asm volatile("ldmatrix.sync.aligned.m8n8.x4.shared.b16 {%0,%1,%2,%3}, [%4];"
                 : "=r"(r[0]), "=r"(r[1]), "=r"(r[2]), "=r"(r[3]) : "r"(addr));
}
__device__ __forceinline__ void mma_fp16(float* c, const unsigned* a,
                                         unsigned b0, unsigned b1) {
    asm volatile(
        "mma.sync.aligned.m16n8k16.row.col.f32.f16.f16.f32 "
        "{%0,%1,%2,%3}, {%4,%5,%6,%7}, {%8,%9}, {%0,%1,%2,%3};"
        : "+f"(c[0]), "+f"(c[1]), "+f"(c[2]), "+f"(c[3])
        : "r"(a[0]), "r"(a[1]), "r"(a[2]), "r"(a[3]), "r"(b0), "r"(b1));
}
__device__ __forceinline__ unsigned pack_f16x2(float lo, float hi) {
    unsigned d;
    asm("cvt.rn.f16x2.f32 %0, %1, %2;" : "=r"(d) : "f"(hi), "f"(lo));
    return d;
}
__device__ __forceinline__ float ex2(float x) {
    float y;
    asm("ex2.approx.f32 %0, %1;" : "=f"(y) : "f"(x));
    return y;
}

// ---------------- weights prep: Wq/Wkv -> fp16 + conv-weight transpose --------
__global__ __launch_bounds__(256) void prep_weights_kernel(
    const float* __restrict__ Wq, const float* __restrict__ Wkv,
    const float* __restrict__ w7, const float* __restrict__ lw) {
    int bx = blockIdx.x, tid = threadIdx.x;
    if (bx < 64) {
        int i = bx * 256 + tid;
        float4 v = ((const float4*)Wq)[i];
        uint2 o;
        o.x = pack_f16x2(v.x, v.y);
        o.y = pack_f16x2(v.z, v.w);
        ((uint2*)g_wqf)[i] = o;
    } else if (bx < 192) {
        int i = (bx - 64) * 256 + tid;
        float4 v = ((const float4*)Wkv)[i];
        uint2 o;
        o.x = pack_f16x2(v.x, v.y);
        o.y = pack_f16x2(v.z, v.w);
        ((uint2*)g_wkvf)[i] = o;
    } else {
        int k = bx - 192;
        g_w7t[k * C + tid] = w7[tid * 49 + k];
        if (k < 9) g_lwt[k * C + tid] = lw[tid * 9 + k];
    }
}

// ---------------- HMMA GEMM fp16 + cp.async double buffer ---------------------
#define GSTR 40
template <int BM, int EPI>
__global__ __launch_bounds__(256, 2) void gemm_mma_kernel(
    const __half* __restrict__ Xf, const __half* __restrict__ Wf,
    const float* __restrict__ bias,
    __half* __restrict__ O1, __half* __restrict__ O2, float scale) {
    constexpr int MT = BM / 64;
    constexpr int SX = BM * GSTR;
    constexpr int SW = 128 * GSTR;
    constexpr int STG = SX + SW;
    extern __shared__ __half gsm[];

    int tid = threadIdx.x, lane = tid & 31, w = tid >> 5;
    int bm = blockIdx.y * BM, bn = blockIdx.x * 128;
    int wm = (w & 3) * (16 * MT), wn = (w >> 2) * 64;
    int lr = tid >> 2, lch = (tid & 3) * 8;

    float acc[MT][8][4];
    #pragma unroll
    for (int mt = 0; mt < MT; mt++)
        #pragma unroll
        for (int nt = 0; nt < 8; nt++)
            #pragma unroll
            for (int q = 0; q < 4; q++) acc[mt][nt][q] = 0.f;

    #define XS(s) (gsm + (s) * STG)
    #define WS(s) (gsm + (s) * STG + SX)

    #define LOAD_STAGE(s, kc) do {                                            \
        _Pragma("unroll")                                                      \
        for (int rr = 0; rr < MT; rr++)                                        \
            cp16(smem_u32(XS(s) + (lr + 64 * rr) * GSTR + lch),                \
                 Xf + (size_t)(bm + lr + 64 * rr) * C + (kc) + lch);           \
        _Pragma("unroll")                                                      \
        for (int rr = 0; rr < 2; rr++)                                         \
            cp16(smem_u32(WS(s) + (lr + 64 * rr) * GSTR + lch),                \
                 Wf + (size_t)(bn + lr + 64 * rr) * C + (kc) + lch);           \
    } while (0)

    LOAD_STAGE(0, 0);
    CP_COMMIT();

    #pragma unroll
    for (int kk = 0; kk < 8; kk++) {
        int s = kk & 1;
        if (kk < 7) {
            LOAD_STAGE(s ^ 1, (kk + 1) * 32);
            CP_COMMIT();
            CP_WAIT(1);
        } else {
            CP_WAIT(0);
        }
        __syncthreads();

        #pragma unroll
        for (int ks = 0; ks < 2; ks++) {
            int acol = ks * 16 + (lane >> 4) * 8;
            int arow = wm + (lane & 15);
            unsigned af[MT][4];
            #pragma unroll
            for (int mt = 0; mt < MT; mt++)
                ldmx4(af[mt], smem_u32(XS(s) + (arow + mt * 16) * GSTR + acol));
            unsigned bf[8][2];
            #pragma unroll
            for (int nt4 = 0; nt4 < 4; nt4++) {
                int brow = wn + nt4 * 16 + (lane & 15);
                unsigned t[4];
                ldmx4(t, smem_u32(WS(s) + brow * GSTR + acol));
                bf[nt4 * 2][0] = t[0]; bf[nt4 * 2][1] = t[2];
                bf[nt4 * 2 + 1][0] = t[1]; bf[nt4 * 2 + 1][1] = t[3];
            }
            #pragma unroll
            for (int mt = 0; mt < MT; mt++)
                #pragma unroll
                for (int nt = 0; nt < 8; nt++)
                    mma_fp16(acc[mt][nt], af[mt], bf[nt][0], bf[nt][1]);
        }
        __syncthreads();
    }

    int r_in = (lane >> 2), c_in = (lane & 3) * 2;
    #pragma unroll
    for (int mt = 0; mt < MT; mt++)
        #pragma unroll
        for (int nt = 0; nt < 8; nt++) {
            int col = bn + wn + nt * 8 + c_in;
            float b0 = bias[col], b1 = bias[col + 1];
            int row0 = bm + wm + mt * 16 + r_in;
            float s00 = (acc[mt][nt][0] + b0) * scale;
            float s01 = (acc[mt][nt][1] + b1) * scale;
            float s10 = (acc[mt][nt][2] + b0) * scale;
            float s11 = (acc[mt][nt][3] + b1) * scale;
            __half* dst;
            size_t i0;
            if (EPI == 0 || col < C) {
                dst = O1;
                i0 = (size_t)row0 * C + col;
            } else {
                dst = O2;
                i0 = (size_t)row0 * C + (col - C);
            }
            *(unsigned*)(dst + i0) = pack_f16x2(s00, s01);
            *(unsigned*)(dst + i0 + 8 * C) = pack_f16x2(s10, s11);
        }
    #undef LOAD_STAGE
    #undef XS
    #undef WS
}

// ---------------- SR conv + fused x fp16 convert (L2 re-read) -----------------
__global__ __launch_bounds__(128) void srconv_kernel(
    const float* __restrict__ x,
    const float* __restrict__ g1, const float* __restrict__ b1,
    const float* __restrict__ m1, const float* __restrict__ v1,
    const float* __restrict__ w2,
    const float* __restrict__ g2, const float* __restrict__ b2,
    const float* __restrict__ m2, const float* __restrict__ v2) {
    int opix = blockIdx.x;
    int b = blockIdx.y;
    int c = threadIdx.x * 2;
    int oy = opix >> 4, ox = opix & 15;
    const float* xb = x + (size_t)b * NPIX * C;
    float s0 = 0.f, s1 = 0.f;

    if (oy >= 1 && ox >= 1) {
        const float* base = xb + (size_t)((oy * 4 - 3) * WIMG + ox * 4 - 3) * C + c;
        #pragma unroll
        for (int ky = 0; ky < 7; ky++) {
            #pragma unroll
            for (int kx = 0; kx < 7; kx++) {
                float2 v = *(const float2*)(base + (size_t)(ky * WIMG + kx) * C);
                float2 wv = *(const float2*)(g_w7t + (ky * 7 + kx) * C + c);
                s0 += v.x * wv.x;
                s1 += v.y * wv.y;
            }
        }
    } else {
        #pragma unroll
        for (int ky = 0; ky < 7; ky++) {
            int iy = oy * 4 - 3 + ky;
            if (iy < 0) continue;
            #pragma unroll
            for (int kx = 0; kx < 7; kx++) {
                int ix = ox * 4 - 3 + kx;
                if (ix < 0) continue;
                float2 v = *(const float2*)(xb + (size_t)(iy * WIMG + ix) * C + c);
                float2 wv = *(const float2*)(g_w7t + (ky * 7 + kx) * C + c);
                s0 += v.x * wv.x;
                s1 += v.y * wv.y;
            }
        }
    }

    {
        size_t pbase = (size_t)b * NPIX * C;
        #pragma unroll
        for (int p = 0; p < 16; p++) {
            int ip = (oy * 4 + (p >> 2)) * WIMG + ox * 4 + (p & 3);
            size_t idx = (size_t)ip * C + c;
            float2 v = *(const float2*)(xb + idx);
            *(unsigned*)(g_xf + pbase + idx) = pack_f16x2(v.x, v.y);
        }
    }

    float sc1a = g1[c] * rsqrtf(v1[c] + EPS);
    float sc1b = g1[c + 1] * rsqrtf(v1[c + 1] + EPS);
    float va = s0 * sc1a + (b1[c] - m1[c] * sc1a);
    float vb = s1 * sc1b + (b1[c + 1] - m1[c + 1] * sc1b);
    va = 0.5f * va * (1.f + erff(va * 0.7071067811865476f));
    vb = 0.5f * vb * (1.f + erff(vb * 0.7071067811865476f));
    va *= w2[c];
    vb *= w2[c + 1];
    float sc2a = g2[c] * rsqrtf(v2[c] + EPS);
    float sc2b = g2[c + 1] * rsqrtf(v2[c + 1] + EPS);
    va = va * sc2a + (b2[c] - m2[c] * sc2a);
    vb = vb * sc2b + (b2[c + 1] - m2[c + 1] * sc2b);
    *(float2*)(g_kvred + ((size_t)b * MRED + opix) * C + c) = make_float2(va, vb);
}

// ---------------- local 3x3 dwconv + residual -> fp16 --------------------------
__global__ __launch_bounds__(128) void localconv_kernel(
    const float* __restrict__ lb) {
    int opix = blockIdx.x;
    int b = blockIdx.y;
    int c = threadIdx.x * 2;
    int y = opix >> 4, xq = opix & 15;
    const float* src = g_kvred + (size_t)b * MRED * C;
    float2 ctr = *(const float2*)(src + (size_t)opix * C + c);
    float s0 = lb[c] + ctr.x;
    float s1 = lb[c + 1] + ctr.y;
    #pragma unroll
    for (int dy = -1; dy <= 1; dy++) {
        int yy = y + dy;
        if (yy < 0 || yy >= 16) continue;
        #pragma unroll
        for (int dx = -1; dx <= 1; dx++) {
            int xx = xq + dx;
            if (xx < 0 || xx >= 16) continue;
            float2 wv = *(const float2*)(g_lwt + ((dy + 1) * 3 + (dx + 1)) * C + c);
            float2 sv = *(const float2*)(src + (size_t)(yy * 16 + xx) * C + c);
            s0 += sv.x * wv.x;
            s1 += sv.y * wv.y;
        }
    }
    *(unsigned*)(g_kv2f + ((size_t)b * MRED + opix) * C + c) = pack_f16x2(s0, s1);
}

// ---------------- flash attention via mma.sync fp16 ----------------------------
#define QSTR 40
#define VSTR 264
#define SM_KF 0
#define SM_VT (SM_KF + 256 * QSTR)
#define ATTN_SMEM ((SM_VT + 32 * VSTR) * 2)

__global__ __launch_bounds__(256, 2) void attn_kernel(float* __restrict__ out) {
    extern __shared__ __half smf[];
    __half* kf = smf + SM_KF;
    __half* vt = smf + SM_VT;

    int tid = threadIdx.x, lane = tid & 31, w = tid >> 5;
    int head = blockIdx.y, b = blockIdx.z;

    for (int i = tid; i < 1024; i += 256) {
        int m = i >> 2, ch = (i & 3) * 8;
        size_t src = (size_t)(b * MRED + m) * C + head * HD + ch;
        *(uint4*)(kf + m * QSTR + ch) = *(const uint4*)(g_kf + src);
    }
    for (int i = tid; i < 256 * 16; i += 256) {
        int m = i >> 4, d2 = (i & 15) * 2;
        __half2 v = *(const __half2*)(
            g_vf + (size_t)(b * MRED + m) * C + head * HD + d2);
        vt[d2 * VSTR + m] = v.x;
        vt[(d2 + 1) * VSTR + m] = v.y;
    }
    __syncthreads();

    int m0 = w * 16;

    #pragma unroll 1
    for (int qq = 0; qq < 4; qq++) {
        int qtile = blockIdx.x * 4 + qq;

        unsigned qf[2][4];
        {
            size_t qbase = (size_t)(b * NPIX + qtile * 128 + m0 + (lane >> 2)) * C
                           + head * HD + (lane & 3) * 2;
            #pragma unroll
            for (int kt = 0; kt < 2; kt++) {
                size_t o0 = qbase + kt * 16;
                qf[kt][0] = *(const unsigned*)(g_qf + o0);
                qf[kt][1] = *(const unsigned*)(g_qf + o0 + 8 * C);
                qf[kt][2] = *(const unsigned*)(g_qf + o0 + 8);
                qf[kt][3] = *(const unsigned*)(g_qf + o0 + 8 * C + 8);
            }
        }

        float m_lo = -1e30f, m_hi = -1e30f, sum_lo = 0.f, sum_hi = 0.f;
        float o[4][4];
        #pragma unroll
        for (int i = 0; i < 4; i++)
            #pragma unroll
            for (int j = 0; j < 4; j++) o[i][j] = 0.f;

        #pragma unroll
        for (int kb = 0; kb < 4; kb++) {
            float s[8][4];
            #pragma unroll
            for (int j = 0; j < 8; j++)
                #pragma unroll
                for (int q = 0; q < 4; q++) s[j][q] = 0.f;
            #pragma unroll
            for (int kt = 0; kt < 2; kt++) {
                int col = kt * 16 + (lane >> 4) * 8;
                #pragma unroll
                for (int jj = 0; jj < 4; jj++) {
                    int row = kb * 64 + jj * 16 + (lane & 15);
                    unsigned t[4];
                    ldmx4(t, smem_u32(kf + row * QSTR + col));
                    mma_fp16(s[2 * jj], qf[kt], t[0], t[2]);
                    mma_fp16(s[2 * jj + 1], qf[kt], t[1], t[3]);
                }
            }
            float bm_lo = -1e30f, bm_hi = -1e30f;
            #pragma unroll
            for (int j = 0; j < 8; j++) {
                bm_lo = fmaxf(bm_lo, fmaxf(s[j][0], s[j][1]));
                bm_hi = fmaxf(bm_hi, fmaxf(s[j][2], s[j][3]));
            }
            bm_lo = fmaxf(bm_lo, __shfl_xor_sync(0xFFFFFFFFu, bm_lo, 1));
            bm_lo = fmaxf(bm_lo, __shfl_xor_sync(0xFFFFFFFFu, bm_lo, 2));
            bm_hi = fmaxf(bm_hi, __shfl_xor_sync(0xFFFFFFFFu, bm_hi, 1));
            bm_hi = fmaxf(bm_hi, __shfl_xor_sync(0xFFFFFFFFu, bm_hi, 2));
            float nm_lo = fmaxf(m_lo, bm_lo);
            float nm_hi = fmaxf(m_hi, bm_hi);
            float corr_lo = ex2(m_lo - nm_lo);
            float corr_hi = ex2(m_hi - nm_hi);
            m_lo = nm_lo; m_hi = nm_hi;
            sum_lo *= corr_lo; sum_hi *= corr_hi;
            #pragma unroll
            for (int dn = 0; dn < 4; dn++) {
                o[dn][0] *= corr_lo; o[dn][1] *= corr_lo;
                o[dn][2] *= corr_hi; o[dn][3] *= corr_hi;
            }
            unsigned pl[8], ph[8];
            #pragma unroll
            for (int j = 0; j < 8; j++) {
                float p0 = ex2(s[j][0] - m_lo);
                float p1 = ex2(s[j][1] - m_lo);
                float p2 = ex2(s[j][2] - m_hi);
                float p3 = ex2(s[j][3] - m_hi);
                sum_lo += p0 + p1;
                sum_hi += p2 + p3;
                pl[j] = pack_f16x2(p0, p1);
                ph[j] = pack_f16x2(p2, p3);
            }
            #pragma unroll
            for (int kt = 0; kt < 4; kt++) {
                unsigned a[4] = {pl[2 * kt], ph[2 * kt],
                                 pl[2 * kt + 1], ph[2 * kt + 1]};
                int kcol = kb * 64 + kt * 16 + (lane >> 4) * 8;
                #pragma unroll
                for (int dn2 = 0; dn2 < 2; dn2++) {
                    int drow = dn2 * 16 + (lane & 15);
                    unsigned t[4];
                    ldmx4(t, smem_u32(vt + drow * VSTR + kcol));
                    mma_fp16(o[2 * dn2], a, t[0], t[2]);
                    mma_fp16(o[2 * dn2 + 1], a, t[1], t[3]);
                }
            }
        }

        sum_lo += __shfl_xor_sync(0xFFFFFFFFu, sum_lo, 1);
        sum_lo += __shfl_xor_sync(0xFFFFFFFFu, sum_lo, 2);
        sum_hi += __shfl_xor_sync(0xFFFFFFFFu, sum_hi, 1);
        sum_hi += __shfl_xor_sync(0xFFFFFFFFu, sum_hi, 2);
        float inv_lo = 1.f / sum_lo;
        float inv_hi = 1.f / sum_hi;
        int r = lane >> 2, cc = (lane & 3) * 2;
        int q0 = qtile * 128 + m0 + r;
        #pragma unroll
        for (int dn = 0; dn < 4; dn++) {
            int d = dn * 8 + cc;
            float2 t0 = make_float2(o[dn][0] * inv_lo, o[dn][1] * inv_lo);
            float2 t1 = make_float2(o[dn][2] * inv_hi, o[dn][3] * inv_hi);
            *(float2*)(out + ((size_t)(b * NPIX + q0)) * C + head * HD + d) = t0;
            *(float2*)(out + ((size_t)(b * NPIX + q0 + 8)) * C + head * HD + d) = t1;
        }
    }
}

// ---------------- launch ------------------------------------------------------
extern "C" void kernel_launch(void* const* d_in, const int* in_sizes, int n_in,
                              void* d_out, int out_size) {
    int base = (n_in >= 19) ? 3 : 1;
    const float* x      = (const float*)d_in[0];
    const float* Wq     = (const float*)d_in[base + 0];
    const float* bq     = (const float*)d_in[base + 1];
    const float* Wkv    = (const float*)d_in[base + 2];
    const float* bkv    = (const float*)d_in[base + 3];
    const float* sr_w1  = (const float*)d_in[base + 4];
    const float* bn1g   = (const float*)d_in[base + 5];
    const float* bn1b   = (const float*)d_in[base + 6];
    const float* bn1m   = (const float*)d_in[base + 7];
    const float* bn1v   = (const float*)d_in[base + 8];
    const float* sr_w2  = (const float*)d_in[base + 9];
    const float* bn2g   = (const float*)d_in[base + 10];
    const float* bn2b   = (const float*)d_in[base + 11];
    const float* bn2m   = (const float*)d_in[base + 12];
    const float* bn2v   = (const float*)d_in[base + 13];
    const float* lw     = (const float*)d_in[base + 14];
    const float* lb     = (const float*)d_in[base + 15];
    float* out = (float*)d_out;

    __half *xf, *wqf, *wkvf, *kv2f, *qf, *kfp, *vfp;
    cudaGetSymbolAddress((void**)&xf, g_xf);
    cudaGetSymbolAddress((void**)&wqf, g_wqf);
    cudaGetSymbolAddress((void**)&wkvf, g_wkvf);
    cudaGetSymbolAddress((void**)&kv2f, g_kv2f);
    cudaGetSymbolAddress((void**)&qf, g_qf);
    cudaGetSymbolAddress((void**)&kfp, g_kf);
    cudaGetSymbolAddress((void**)&vfp, g_vf);

    const int smem128 = 2 * (128 * GSTR + 128 * GSTR) * 2;  // 40960
    const int smem64  = 2 * (64 * GSTR + 128 * GSTR) * 2;   // 30720
    cudaFuncSetAttribute((const void*)gemm_mma_kernel<128, 0>,
                         cudaFuncAttributeMaxDynamicSharedMemorySize, smem128);
    cudaFuncSetAttribute((const void*)gemm_mma_kernel<64, 1>,
                         cudaFuncAttributeMaxDynamicSharedMemorySize, smem64);
    cudaFuncSetAttribute((const void*)attn_kernel,
                         cudaFuncAttributeMaxDynamicSharedMemorySize, ATTN_SMEM);

    const float QSC = ATTN_SCALE * 1.4426950408889634f;

    // side stream + events for fork/join (created fresh; kernel_launch is
    // invoked only for the correctness run and the capture run)
    cudaStream_t s2;
    cudaStreamCreate(&s2);
    cudaEvent_t evFork, evJoin;
    cudaEventCreateWithFlags(&evFork, cudaEventDisableTiming);
    cudaEventCreateWithFlags(&evJoin, cudaEventDisableTiming);

    prep_weights_kernel<<<192 + 49, 256>>>(Wq, Wkv, sr_w1, lw);
    srconv_kernel<<<dim3(MRED, BATCH), 128>>>(x, bn1g, bn1b, bn1m, bn1v,
                                              sr_w2, bn2g, bn2b, bn2m, bn2v);
    // fork: q projection (reads g_xf from srconv, g_wqf from prep)
    cudaEventRecord(evFork, 0);
    cudaStreamWaitEvent(s2, evFork, 0);
    gemm_mma_kernel<128, 0><<<dim3(C / 128, BATCH * NPIX / 128), 256, smem128,
                              s2>>>(xf, wqf, bq, qf, nullptr, QSC);
    cudaEventRecord(evJoin, s2);
    // main branch: kv pipeline
    localconv_kernel<<<dim3(MRED, BATCH), 128>>>(lb);
    gemm_mma_kernel<64, 1><<<dim3(2 * C / 128, BATCH * MRED / 64), 256, smem64>>>(
        kv2f, wkvf, bkv, kfp, vfp, 1.0f);
    // join, then attention
    cudaStreamWaitEvent(0, evJoin, 0);
    attn_kernel<<<dim3(NPIX / 512, HEADS, BATCH), 256, ATTN_SMEM>>>(out);
}